// round 11
// baseline (speedup 1.0000x reference)
#include <cuda_runtime.h>
#include <math.h>

// Learned optimizer step. Inputs (metadata order):
// 0 grad[N] 1 state0[N] 2 state1[N] 3 loss_cur[1] 4 loss_old[1] 5 iteration[1]
// 6 gradient_param[N] 7 extrapolation[N]
// 8 cw0[20x4] 9 cb0[20] 10 cw1[20x20] 11 cb1[20] 12 cw2[20x20] 13 cb2[20]
// 14 cw3[1x20] 15 cb3[1]
// 16 lw0[30x6] 17 lb0[30] 18 lw1[20x30] 19 lb1[20] 20 lw2[10x20] 21 lb2[10]
// 22 lw3[4x10] 23 lb3[4]
// Output: float32 [N]
//
// Main kernel: 2 elements/thread packed into f32x2 (SASS FFMA2 — 2 FMAs per
// fma-pipe issue, halving the FFMA issue count vs Round 8's scalar floor).
// Activations live in registers as u64 {u,v} pairs; weights in shared
// pre-duplicated as float2{w,w} (one LDS.128 = two packed weight operands).
// __launch_bounds__(128, 2) gives ptxas a 255-reg budget (proven in R8 to
// defeat the 32-reg occupancy squeeze that spilled earlier attempts).
// [Resubmit of R9 — prior run died to a broker/container failure, not a
// kernel failure; no evidence against this design exists yet.]

#define RED_BLOCKS 1024
#define RED_THREADS 256
#define MAIN_THREADS 128

typedef unsigned long long u64;

__device__ float4 g_part[RED_BLOCKS];
__device__ unsigned int g_ticket = 0;
__device__ float g_coeff0, g_coeff1, g_coeff2, g_coeff3;
__device__ float g_inv_gn;
__device__ float g_inv_dn;
__device__ float g_fscale;

// ---------- packed f32x2 helpers ----------
__device__ __forceinline__ u64 f2fma(u64 a, u64 b, u64 c) {
    u64 d;
    asm("fma.rn.f32x2 %0, %1, %2, %3;" : "=l"(d) : "l"(a), "l"(b), "l"(c));
    return d;
}
__device__ __forceinline__ u64 pk(float lo, float hi) {
    u64 r;
    asm("mov.b64 %0, {%1, %2};" : "=l"(r) : "f"(lo), "f"(hi));
    return r;
}
__device__ __forceinline__ float2 upk(u64 v) {
    float2 r;
    asm("mov.b64 {%0, %1}, %2;" : "=f"(r.x), "=f"(r.y) : "l"(v));
    return r;
}
__device__ __forceinline__ u64 relu2(u64 v) {
    float2 t = upk(v);
    return pk(fmaxf(t.x, 0.0f), fmaxf(t.y, 0.0f));
}

// ---------------------------------------------------------------------------
// Kernel A (fused): block partial reductions + last-block finalize
// ---------------------------------------------------------------------------
__global__ void reduce_scalars_kernel(
    const float* __restrict__ grad, const float* __restrict__ s0,
    const float* __restrict__ s1, int n,
    const float* __restrict__ loss_cur, const float* __restrict__ loss_old,
    const int* __restrict__ iter_p,
    const float* __restrict__ lw0, const float* __restrict__ lb0,
    const float* __restrict__ lw1, const float* __restrict__ lb1,
    const float* __restrict__ lw2, const float* __restrict__ lb2,
    const float* __restrict__ lw3, const float* __restrict__ lb3) {
    __shared__ float4 sh[RED_THREADS / 32];
    __shared__ int s_last;
    __shared__ float sfeat[6];
    __shared__ float sh0[30];
    __shared__ float sh1[20];
    __shared__ float sh2[10];

    int tid = threadIdx.x;
    int n4 = n >> 2;
    float sg2 = 0.f, sd2 = 0.f, sgd = 0.f, amax = 0.f;
    for (int i = blockIdx.x * blockDim.x + tid; i < n4;
         i += gridDim.x * blockDim.x) {
        float4 g = ((const float4*)grad)[i];
        float4 a = ((const float4*)s0)[i];
        float4 b = ((const float4*)s1)[i];
        float dx = b.x - a.x, dy = b.y - a.y, dz = b.z - a.z, dw = b.w - a.w;
        sg2 += g.x * g.x + g.y * g.y + g.z * g.z + g.w * g.w;
        sd2 += dx * dx + dy * dy + dz * dz + dw * dw;
        sgd += g.x * dx + g.y * dy + g.z * dz + g.w * dw;
        amax = fmaxf(amax, fmaxf(fmaxf(fabsf(g.x), fabsf(g.y)),
                                 fmaxf(fabsf(g.z), fabsf(g.w))));
    }
    #pragma unroll
    for (int off = 16; off; off >>= 1) {
        sg2 += __shfl_down_sync(0xffffffffu, sg2, off);
        sd2 += __shfl_down_sync(0xffffffffu, sd2, off);
        sgd += __shfl_down_sync(0xffffffffu, sgd, off);
        amax = fmaxf(amax, __shfl_down_sync(0xffffffffu, amax, off));
    }
    int lane = tid & 31, w = tid >> 5;
    if (!lane) sh[w] = make_float4(sg2, sd2, sgd, amax);
    __syncthreads();
    if (tid == 0) {
        float4 v = sh[0];
        #pragma unroll
        for (int i = 1; i < RED_THREADS / 32; i++) {
            float4 q = sh[i];
            v.x += q.x; v.y += q.y; v.z += q.z; v.w = fmaxf(v.w, q.w);
        }
        g_part[blockIdx.x] = v;
        __threadfence();
        unsigned int old = atomicInc(&g_ticket, RED_BLOCKS - 1);
        s_last = (old == RED_BLOCKS - 1);
    }
    __syncthreads();
    if (!s_last) return;

    sg2 = 0.f; sd2 = 0.f; sgd = 0.f; amax = 0.f;
    for (int i = tid; i < RED_BLOCKS; i += RED_THREADS) {
        float4 p = g_part[i];
        sg2 += p.x; sd2 += p.y; sgd += p.z; amax = fmaxf(amax, p.w);
    }
    #pragma unroll
    for (int off = 16; off; off >>= 1) {
        sg2 += __shfl_down_sync(0xffffffffu, sg2, off);
        sd2 += __shfl_down_sync(0xffffffffu, sd2, off);
        sgd += __shfl_down_sync(0xffffffffu, sgd, off);
        amax = fmaxf(amax, __shfl_down_sync(0xffffffffu, amax, off));
    }
    __syncthreads();
    if (!lane) sh[w] = make_float4(sg2, sd2, sgd, amax);
    __syncthreads();

    if (tid == 0) {
        float4 v = sh[0];
        #pragma unroll
        for (int i = 1; i < RED_THREADS / 32; i++) {
            float4 q = sh[i];
            v.x += q.x; v.y += q.y; v.z += q.z; v.w = fmaxf(v.w, q.w);
        }
        float gn = sqrtf(v.x);
        float dn = sqrtf(v.y);
        float inv_gn = (gn > 1e-10f) ? (1.0f / gn) : 1.0f;
        float inv_dn = (dn > 1e-10f) ? (1.0f / dn) : 1.0f;
        float it = (float)iter_p[0];
        sfeat[0] = log1pf(gn);
        sfeat[1] = log1pf(dn);
        sfeat[2] = v.z * inv_gn * inv_dn;
        sfeat[3] = v.w * inv_gn;
        sfeat[4] = it;
        sfeat[5] = logf(loss_cur[0]) - logf(loss_old[0]);
        g_inv_gn = inv_gn;
        g_inv_dn = inv_dn;
        g_fscale = 1.0f / sqrtf(1.0f + it);
    }
    __syncthreads();

    if (tid < 30) {
        float a = lb0[tid];
        #pragma unroll
        for (int f = 0; f < 6; f++) a = fmaf(lw0[tid * 6 + f], sfeat[f], a);
        sh0[tid] = fmaxf(a, 0.0f);
    }
    __syncthreads();
    if (tid < 20) {
        float a = lb1[tid];
        #pragma unroll
        for (int c = 0; c < 30; c++) a = fmaf(lw1[tid * 30 + c], sh0[c], a);
        sh1[tid] = fmaxf(a, 0.0f);
    }
    __syncthreads();
    if (tid < 10) {
        float a = lb2[tid];
        #pragma unroll
        for (int c = 0; c < 20; c++) a = fmaf(lw2[tid * 20 + c], sh1[c], a);
        sh2[tid] = fmaxf(a, 0.0f);
    }
    __syncthreads();
    if (tid < 4) {
        float a = lb3[tid];
        #pragma unroll
        for (int c = 0; c < 10; c++) a = fmaf(lw3[tid * 10 + c], sh2[c], a);
        if (tid == 0) g_coeff0 = a;
        if (tid == 1) g_coeff1 = a;
        if (tid == 2) g_coeff2 = a;
        if (tid == 3) g_coeff3 = a;
    }
}

// ---------------------------------------------------------------------------
// Kernel B: per-element MLP 4->20->20->20->1, 2 elements/thread via f32x2,
// half-layer (10-output) accumulation, activations as u64 {u,v} pairs.
// Shared weight rows: 10 x float2{w,w} = 80B, 16B-aligned -> 5 LDS.128/row,
// each feeding 2 FFMA2.
// ---------------------------------------------------------------------------

// A0..A9 += weight-row (10 dup-pairs) * T
#define ACCROWH(ROWPTR, T) { \
    const ulonglong2* r_ = (const ulonglong2*)(ROWPTR); \
    ulonglong2 w0 = r_[0], w1 = r_[1], w2 = r_[2], w3 = r_[3], w4 = r_[4]; \
    A0 = f2fma(w0.x, (T), A0); A1 = f2fma(w0.y, (T), A1); \
    A2 = f2fma(w1.x, (T), A2); A3 = f2fma(w1.y, (T), A3); \
    A4 = f2fma(w2.x, (T), A4); A5 = f2fma(w2.y, (T), A5); \
    A6 = f2fma(w3.x, (T), A6); A7 = f2fma(w3.y, (T), A7); \
    A8 = f2fma(w4.x, (T), A8); A9 = f2fma(w4.y, (T), A9); }

#define BIASH(SB) { \
    const ulonglong2* b_ = (const ulonglong2*)(SB); \
    ulonglong2 q0 = b_[0], q1 = b_[1], q2 = b_[2], q3 = b_[3], q4 = b_[4]; \
    A0 = q0.x; A1 = q0.y; A2 = q1.x; A3 = q1.y; A4 = q2.x; \
    A5 = q2.y; A6 = q3.x; A7 = q3.y; A8 = q4.x; A9 = q4.y; }

#define RELU_A(P) \
    P##0 = relu2(A0); P##1 = relu2(A1); P##2 = relu2(A2); P##3 = relu2(A3); \
    P##4 = relu2(A4); P##5 = relu2(A5); P##6 = relu2(A6); P##7 = relu2(A7); \
    P##8 = relu2(A8); P##9 = relu2(A9);

#define RELU_B(P) \
    P##10 = relu2(A0); P##11 = relu2(A1); P##12 = relu2(A2); P##13 = relu2(A3); \
    P##14 = relu2(A4); P##15 = relu2(A5); P##16 = relu2(A6); P##17 = relu2(A7); \
    P##18 = relu2(A8); P##19 = relu2(A9);

#define HALF20(SW, SB, IP) \
    BIASH(SB) \
    ACCROWH(&(SW)[0][0],  IP##0)  ACCROWH(&(SW)[1][0],  IP##1) \
    ACCROWH(&(SW)[2][0],  IP##2)  ACCROWH(&(SW)[3][0],  IP##3) \
    ACCROWH(&(SW)[4][0],  IP##4)  ACCROWH(&(SW)[5][0],  IP##5) \
    ACCROWH(&(SW)[6][0],  IP##6)  ACCROWH(&(SW)[7][0],  IP##7) \
    ACCROWH(&(SW)[8][0],  IP##8)  ACCROWH(&(SW)[9][0],  IP##9) \
    ACCROWH(&(SW)[10][0], IP##10) ACCROWH(&(SW)[11][0], IP##11) \
    ACCROWH(&(SW)[12][0], IP##12) ACCROWH(&(SW)[13][0], IP##13) \
    ACCROWH(&(SW)[14][0], IP##14) ACCROWH(&(SW)[15][0], IP##15) \
    ACCROWH(&(SW)[16][0], IP##16) ACCROWH(&(SW)[17][0], IP##17) \
    ACCROWH(&(SW)[18][0], IP##18) ACCROWH(&(SW)[19][0], IP##19)

#define DECL20(P) \
    u64 P##0, P##1, P##2, P##3, P##4, P##5, P##6, P##7, P##8, P##9, \
        P##10, P##11, P##12, P##13, P##14, P##15, P##16, P##17, P##18, P##19;

__global__ void __launch_bounds__(MAIN_THREADS, 2) main_kernel(
    const float* __restrict__ grad, const float* __restrict__ s0,
    const float* __restrict__ s1, const float* __restrict__ gp,
    const float* __restrict__ ex,
    const float* __restrict__ cw0, const float* __restrict__ cb0,
    const float* __restrict__ cw1, const float* __restrict__ cb1,
    const float* __restrict__ cw2, const float* __restrict__ cb2,
    const float* __restrict__ cw3, const float* __restrict__ cb3,
    float* __restrict__ out, int n) {
    // weights: duplicated pairs {w,w}; rows = input channel, 10 pairs = 80B
    __shared__ __align__(16) float2 sw0a[4][10],  sw0b[4][10];
    __shared__ __align__(16) float2 sw1a[20][10], sw1b[20][10];
    __shared__ __align__(16) float2 sw2a[20][10], sw2b[20][10];
    __shared__ __align__(16) float2 sw3[20];
    __shared__ __align__(16) float2 sb0a[10], sb0b[10];
    __shared__ __align__(16) float2 sb1a[10], sb1b[10];
    __shared__ __align__(16) float2 sb2a[10], sb2b[10];
    __shared__ float sb3f;

    int tid = threadIdx.x;

    // ---- stage weights (transposed, halved, dup-paired; coeff/fscale folded)
    if (tid < 40) {
        int c = tid / 10, j = tid % 10;
        float c0 = g_coeff0, c1 = g_coeff1, c2 = g_coeff2, c3 = g_coeff3;
        float cf = (c == 0) ? c0 : (c == 1) ? c1 : (c == 2) ? c2 : c3;
        float wa = cw0[j * 4 + c] * cf;
        float wb = cw0[(j + 10) * 4 + c] * cf;
        sw0a[c][j] = make_float2(wa, wa);
        sw0b[c][j] = make_float2(wb, wb);
    }
    for (int k = tid; k < 200; k += MAIN_THREADS) {
        int c = k / 10, j = k % 10;
        float w1a = cw1[j * 20 + c];
        float w1b = cw1[(j + 10) * 20 + c];
        float w2a = cw2[j * 20 + c];
        float w2b = cw2[(j + 10) * 20 + c];
        sw1a[c][j] = make_float2(w1a, w1a);
        sw1b[c][j] = make_float2(w1b, w1b);
        sw2a[c][j] = make_float2(w2a, w2a);
        sw2b[c][j] = make_float2(w2b, w2b);
    }
    if (tid < 10) {
        float b;
        b = cb0[tid];      sb0a[tid] = make_float2(b, b);
        b = cb0[tid + 10]; sb0b[tid] = make_float2(b, b);
        b = cb1[tid];      sb1a[tid] = make_float2(b, b);
        b = cb1[tid + 10]; sb1b[tid] = make_float2(b, b);
        b = cb2[tid];      sb2a[tid] = make_float2(b, b);
        b = cb2[tid + 10]; sb2b[tid] = make_float2(b, b);
    }
    if (tid < 20) {
        float wv = cw3[tid] * g_fscale;
        sw3[tid] = make_float2(wv, wv);
    }
    if (tid == 0) sb3f = cb3[0] * g_fscale;
    __syncthreads();

    int p = blockIdx.x * MAIN_THREADS + tid;
    int npair = n >> 1;
    if (p >= npair) return;

    float inv_gn = g_inv_gn, inv_dn = g_inv_dn;

    float2 g2 = ((const float2*)grad)[p];
    float2 a2 = ((const float2*)s0)[p];
    float2 b2 = ((const float2*)s1)[p];
    float2 p2 = ((const float2*)gp)[p];
    float2 e2 = ((const float2*)ex)[p];

    float gxu = g2.x * inv_gn, gxv = g2.y * inv_gn;
    float dxu = (b2.x - a2.x) * inv_dn, dxv = (b2.y - a2.y) * inv_dn;

    u64 t0 = pk(p2.x * gxu, p2.y * gxv);  // gradient_param * g
    u64 t1 = pk(e2.x * dxu, e2.y * dxv);  // extrapolation * d
    u64 t2 = pk(gxu, gxv);                // g
    u64 t3 = pk(dxu, dxv);                // d

    u64 A0, A1, A2, A3, A4, A5, A6, A7, A8, A9;
    DECL20(H)
    DECL20(G)

    // ---- layer 0: 4 -> 20 (two halves; coeff folded into sw0) ----
    BIASH(sb0a)
    ACCROWH(&sw0a[0][0], t0) ACCROWH(&sw0a[1][0], t1)
    ACCROWH(&sw0a[2][0], t2) ACCROWH(&sw0a[3][0], t3)
    RELU_A(H)
    BIASH(sb0b)
    ACCROWH(&sw0b[0][0], t0) ACCROWH(&sw0b[1][0], t1)
    ACCROWH(&sw0b[2][0], t2) ACCROWH(&sw0b[3][0], t3)
    RELU_B(H)

    // ---- layer 1: 20 -> 20 (H -> G) ----
    HALF20(sw1a, sb1a, H)
    RELU_A(G)
    HALF20(sw1b, sb1b, H)
    RELU_B(G)

    // ---- layer 2: 20 -> 20 (G -> H) ----
    HALF20(sw2a, sb2a, G)
    RELU_A(H)
    HALF20(sw2b, sb2b, G)
    RELU_B(H)

    // ---- layer 3: 20 -> 1 (fscale folded into sw3/sb3) ----
    u64 acA = pk(sb3f, sb3f);
    u64 acB = pk(0.0f, 0.0f);
    {
        const ulonglong2* wp = (const ulonglong2*)sw3;
        ulonglong2 w_;
        w_ = wp[0]; acA = f2fma(w_.x, H0,  acA); acB = f2fma(w_.y, H1,  acB);
        w_ = wp[1]; acA = f2fma(w_.x, H2,  acA); acB = f2fma(w_.y, H3,  acB);
        w_ = wp[2]; acA = f2fma(w_.x, H4,  acA); acB = f2fma(w_.y, H5,  acB);
        w_ = wp[3]; acA = f2fma(w_.x, H6,  acA); acB = f2fma(w_.y, H7,  acB);
        w_ = wp[4]; acA = f2fma(w_.x, H8,  acA); acB = f2fma(w_.y, H9,  acB);
        w_ = wp[5]; acA = f2fma(w_.x, H10, acA); acB = f2fma(w_.y, H11, acB);
        w_ = wp[6]; acA = f2fma(w_.x, H12, acA); acB = f2fma(w_.y, H13, acB);
        w_ = wp[7]; acA = f2fma(w_.x, H14, acA); acB = f2fma(w_.y, H15, acB);
        w_ = wp[8]; acA = f2fma(w_.x, H16, acA); acB = f2fma(w_.y, H17, acB);
        w_ = wp[9]; acA = f2fma(w_.x, H18, acA); acB = f2fma(w_.y, H19, acB);
    }
    float2 ra = upk(acA), rb = upk(acB);
    float2 o2;
    o2.x = b2.x + (ra.x + rb.x);
    o2.y = b2.y + (ra.y + rb.y);
    ((float2*)out)[p] = o2;
}

// ---------------------------------------------------------------------------
extern "C" void kernel_launch(void* const* d_in, const int* in_sizes, int n_in,
                              void* d_out, int out_size) {
    const float* grad = (const float*)d_in[0];
    const float* s0   = (const float*)d_in[1];
    const float* s1   = (const float*)d_in[2];
    const float* loss_cur = (const float*)d_in[3];
    const float* loss_old = (const float*)d_in[4];
    const int*   iter_p   = (const int*)d_in[5];
    const float* gp = (const float*)d_in[6];
    const float* ex = (const float*)d_in[7];
    const float* cw0 = (const float*)d_in[8];
    const float* cb0 = (const float*)d_in[9];
    const float* cw1 = (const float*)d_in[10];
    const float* cb1 = (const float*)d_in[11];
    const float* cw2 = (const float*)d_in[12];
    const float* cb2 = (const float*)d_in[13];
    const float* cw3 = (const float*)d_in[14];
    const float* cb3 = (const float*)d_in[15];
    const float* lw0 = (const float*)d_in[16];
    const float* lb0 = (const float*)d_in[17];
    const float* lw1 = (const float*)d_in[18];
    const float* lb1 = (const float*)d_in[19];
    const float* lw2 = (const float*)d_in[20];
    const float* lb2 = (const float*)d_in[21];
    const float* lw3 = (const float*)d_in[22];
    const float* lb3 = (const float*)d_in[23];

    int n = in_sizes[0];
    int npair = n >> 1;
    int main_blocks = (npair + MAIN_THREADS - 1) / MAIN_THREADS;
    if (main_blocks < 1) main_blocks = 1;

    reduce_scalars_kernel<<<RED_BLOCKS, RED_THREADS>>>(
        grad, s0, s1, n, loss_cur, loss_old, iter_p,
        lw0, lb0, lw1, lb1, lw2, lb2, lw3, lb3);
    main_kernel<<<main_blocks, MAIN_THREADS>>>(grad, s0, s1, gp, ex,
                                               cw0, cb0, cw1, cb1, cw2, cb2,
                                               cw3, cb3, (float*)d_out, n);
}

// round 12
// speedup vs baseline: 1.4670x; 1.4670x over previous
#include <cuda_runtime.h>
#include <math.h>

// Learned optimizer step. Inputs (metadata order):
// 0 grad[N] 1 state0[N] 2 state1[N] 3 loss_cur[1] 4 loss_old[1] 5 iteration[1]
// 6 gradient_param[N] 7 extrapolation[N]
// 8 cw0[20x4] 9 cb0[20] 10 cw1[20x20] 11 cb1[20] 12 cw2[20x20] 13 cb2[20]
// 14 cw3[1x20] 15 cb3[1]
// 16 lw0[30x6] 17 lb0[30] 18 lw1[20x30] 19 lb1[20] 20 lw2[10x20] 21 lb2[10]
// 22 lw3[4x10] 23 lb3[4]
// Output: float32 [N]
//
// Main kernel: 2 elements/thread, FFMA2 (fma.rn.f32x2) with OUTPUT-PAIR
// packed accumulators: each u64 = two adjacent outputs of one element, so
// weight operands are natural adjacent pairs from a transposed 20-float row
// (80 B/row, NO duplication — halves the LDS bytes that made R11 L1-bound
// at 98%). Both elements share every weight load. Activation multipliers
// {h,h} are built transiently per channel (cheap alu MOVs, overlapped).

#define RED_BLOCKS 1024
#define RED_THREADS 256
#define MAIN_THREADS 128

typedef unsigned long long u64;

__device__ float4 g_part[RED_BLOCKS];
__device__ unsigned int g_ticket = 0;
__device__ float g_coeff0, g_coeff1, g_coeff2, g_coeff3;
__device__ float g_inv_gn;
__device__ float g_inv_dn;
__device__ float g_fscale;

// ---------- packed f32x2 helpers ----------
__device__ __forceinline__ u64 f2fma(u64 a, u64 b, u64 c) {
    u64 d;
    asm("fma.rn.f32x2 %0, %1, %2, %3;" : "=l"(d) : "l"(a), "l"(b), "l"(c));
    return d;
}
__device__ __forceinline__ u64 pk(float lo, float hi) {
    u64 r;
    asm("mov.b64 %0, {%1, %2};" : "=l"(r) : "f"(lo), "f"(hi));
    return r;
}
__device__ __forceinline__ float2 upk(u64 v) {
    float2 r;
    asm("mov.b64 {%0, %1}, %2;" : "=f"(r.x), "=f"(r.y) : "l"(v));
    return r;
}
__device__ __forceinline__ u64 relu2(u64 v) {
    float2 t = upk(v);
    return pk(fmaxf(t.x, 0.0f), fmaxf(t.y, 0.0f));
}

// ---------------------------------------------------------------------------
// Kernel A (fused): block partial reductions + last-block finalize
// ---------------------------------------------------------------------------
__global__ void reduce_scalars_kernel(
    const float* __restrict__ grad, const float* __restrict__ s0,
    const float* __restrict__ s1, int n,
    const float* __restrict__ loss_cur, const float* __restrict__ loss_old,
    const int* __restrict__ iter_p,
    const float* __restrict__ lw0, const float* __restrict__ lb0,
    const float* __restrict__ lw1, const float* __restrict__ lb1,
    const float* __restrict__ lw2, const float* __restrict__ lb2,
    const float* __restrict__ lw3, const float* __restrict__ lb3) {
    __shared__ float4 sh[RED_THREADS / 32];
    __shared__ int s_last;
    __shared__ float sfeat[6];
    __shared__ float sh0[30];
    __shared__ float sh1[20];
    __shared__ float sh2[10];

    int tid = threadIdx.x;
    int n4 = n >> 2;
    float sg2 = 0.f, sd2 = 0.f, sgd = 0.f, amax = 0.f;
    for (int i = blockIdx.x * blockDim.x + tid; i < n4;
         i += gridDim.x * blockDim.x) {
        float4 g = ((const float4*)grad)[i];
        float4 a = ((const float4*)s0)[i];
        float4 b = ((const float4*)s1)[i];
        float dx = b.x - a.x, dy = b.y - a.y, dz = b.z - a.z, dw = b.w - a.w;
        sg2 += g.x * g.x + g.y * g.y + g.z * g.z + g.w * g.w;
        sd2 += dx * dx + dy * dy + dz * dz + dw * dw;
        sgd += g.x * dx + g.y * dy + g.z * dz + g.w * dw;
        amax = fmaxf(amax, fmaxf(fmaxf(fabsf(g.x), fabsf(g.y)),
                                 fmaxf(fabsf(g.z), fabsf(g.w))));
    }
    #pragma unroll
    for (int off = 16; off; off >>= 1) {
        sg2 += __shfl_down_sync(0xffffffffu, sg2, off);
        sd2 += __shfl_down_sync(0xffffffffu, sd2, off);
        sgd += __shfl_down_sync(0xffffffffu, sgd, off);
        amax = fmaxf(amax, __shfl_down_sync(0xffffffffu, amax, off));
    }
    int lane = tid & 31, w = tid >> 5;
    if (!lane) sh[w] = make_float4(sg2, sd2, sgd, amax);
    __syncthreads();
    if (tid == 0) {
        float4 v = sh[0];
        #pragma unroll
        for (int i = 1; i < RED_THREADS / 32; i++) {
            float4 q = sh[i];
            v.x += q.x; v.y += q.y; v.z += q.z; v.w = fmaxf(v.w, q.w);
        }
        g_part[blockIdx.x] = v;
        __threadfence();
        unsigned int old = atomicInc(&g_ticket, RED_BLOCKS - 1);
        s_last = (old == RED_BLOCKS - 1);
    }
    __syncthreads();
    if (!s_last) return;

    sg2 = 0.f; sd2 = 0.f; sgd = 0.f; amax = 0.f;
    for (int i = tid; i < RED_BLOCKS; i += RED_THREADS) {
        float4 p = g_part[i];
        sg2 += p.x; sd2 += p.y; sgd += p.z; amax = fmaxf(amax, p.w);
    }
    #pragma unroll
    for (int off = 16; off; off >>= 1) {
        sg2 += __shfl_down_sync(0xffffffffu, sg2, off);
        sd2 += __shfl_down_sync(0xffffffffu, sd2, off);
        sgd += __shfl_down_sync(0xffffffffu, sgd, off);
        amax = fmaxf(amax, __shfl_down_sync(0xffffffffu, amax, off));
    }
    __syncthreads();
    if (!lane) sh[w] = make_float4(sg2, sd2, sgd, amax);
    __syncthreads();

    if (tid == 0) {
        float4 v = sh[0];
        #pragma unroll
        for (int i = 1; i < RED_THREADS / 32; i++) {
            float4 q = sh[i];
            v.x += q.x; v.y += q.y; v.z += q.z; v.w = fmaxf(v.w, q.w);
        }
        float gn = sqrtf(v.x);
        float dn = sqrtf(v.y);
        float inv_gn = (gn > 1e-10f) ? (1.0f / gn) : 1.0f;
        float inv_dn = (dn > 1e-10f) ? (1.0f / dn) : 1.0f;
        float it = (float)iter_p[0];
        sfeat[0] = log1pf(gn);
        sfeat[1] = log1pf(dn);
        sfeat[2] = v.z * inv_gn * inv_dn;
        sfeat[3] = v.w * inv_gn;
        sfeat[4] = it;
        sfeat[5] = logf(loss_cur[0]) - logf(loss_old[0]);
        g_inv_gn = inv_gn;
        g_inv_dn = inv_dn;
        g_fscale = 1.0f / sqrtf(1.0f + it);
    }
    __syncthreads();

    if (tid < 30) {
        float a = lb0[tid];
        #pragma unroll
        for (int f = 0; f < 6; f++) a = fmaf(lw0[tid * 6 + f], sfeat[f], a);
        sh0[tid] = fmaxf(a, 0.0f);
    }
    __syncthreads();
    if (tid < 20) {
        float a = lb1[tid];
        #pragma unroll
        for (int c = 0; c < 30; c++) a = fmaf(lw1[tid * 30 + c], sh0[c], a);
        sh1[tid] = fmaxf(a, 0.0f);
    }
    __syncthreads();
    if (tid < 10) {
        float a = lb2[tid];
        #pragma unroll
        for (int c = 0; c < 20; c++) a = fmaf(lw2[tid * 20 + c], sh1[c], a);
        sh2[tid] = fmaxf(a, 0.0f);
    }
    __syncthreads();
    if (tid < 4) {
        float a = lb3[tid];
        #pragma unroll
        for (int c = 0; c < 10; c++) a = fmaf(lw3[tid * 10 + c], sh2[c], a);
        if (tid == 0) g_coeff0 = a;
        if (tid == 1) g_coeff1 = a;
        if (tid == 2) g_coeff2 = a;
        if (tid == 3) g_coeff3 = a;
    }
}

// ---------------------------------------------------------------------------
// Kernel B: per-element MLP 4->20->20->20->1, 2 elements/thread (u, v).
// Accumulators: Au_k/Av_k = outputs {2k, 2k+1} of elem u/v (output-pair
// packing). Weight rows are natural 20-float transposed rows (5 quads,
// shared by both elements). Multipliers are transient {h,h} dup-pairs.
// ---------------------------------------------------------------------------

// All 10 output-pairs of both elems += natural weight row * {DU, DV}
#define ACCROW2(ROWPTR, DU, DV) { \
    const ulonglong2* r_ = (const ulonglong2*)(ROWPTR); \
    ulonglong2 w0 = r_[0], w1 = r_[1], w2 = r_[2], w3 = r_[3], w4 = r_[4]; \
    Au0 = f2fma(w0.x, (DU), Au0); Av0 = f2fma(w0.x, (DV), Av0); \
    Au1 = f2fma(w0.y, (DU), Au1); Av1 = f2fma(w0.y, (DV), Av1); \
    Au2 = f2fma(w1.x, (DU), Au2); Av2 = f2fma(w1.x, (DV), Av2); \
    Au3 = f2fma(w1.y, (DU), Au3); Av3 = f2fma(w1.y, (DV), Av3); \
    Au4 = f2fma(w2.x, (DU), Au4); Av4 = f2fma(w2.x, (DV), Av4); \
    Au5 = f2fma(w2.y, (DU), Au5); Av5 = f2fma(w2.y, (DV), Av5); \
    Au6 = f2fma(w3.x, (DU), Au6); Av6 = f2fma(w3.x, (DV), Av6); \
    Au7 = f2fma(w3.y, (DU), Au7); Av7 = f2fma(w3.y, (DV), Av7); \
    Au8 = f2fma(w4.x, (DU), Au8); Av8 = f2fma(w4.x, (DV), Av8); \
    Au9 = f2fma(w4.y, (DU), Au9); Av9 = f2fma(w4.y, (DV), Av9); }

// Channels 2K and 2K+1: extract scalars from H pair K, dup, accumulate.
#define CH2(SW, K) { \
    float2 hu_ = upk(Hu##K); float2 hv_ = upk(Hv##K); \
    u64 du_ = pk(hu_.x, hu_.x); u64 dv_ = pk(hv_.x, hv_.x); \
    ACCROW2(&(SW)[2 * (K)][0], du_, dv_); \
    du_ = pk(hu_.y, hu_.y); dv_ = pk(hv_.y, hv_.y); \
    ACCROW2(&(SW)[2 * (K) + 1][0], du_, dv_); }

#define LAYER20N(SW) \
    CH2(SW, 0) CH2(SW, 1) CH2(SW, 2) CH2(SW, 3) CH2(SW, 4) \
    CH2(SW, 5) CH2(SW, 6) CH2(SW, 7) CH2(SW, 8) CH2(SW, 9)

// Bias init: natural pairs {b_2k, b_2k+1} into both elems' accumulators.
#define BIASN(SB) { \
    const ulonglong2* b_ = (const ulonglong2*)(SB); \
    ulonglong2 q0 = b_[0], q1 = b_[1], q2 = b_[2], q3 = b_[3], q4 = b_[4]; \
    Au0 = q0.x; Au1 = q0.y; Au2 = q1.x; Au3 = q1.y; Au4 = q2.x; \
    Au5 = q2.y; Au6 = q3.x; Au7 = q3.y; Au8 = q4.x; Au9 = q4.y; \
    Av0 = Au0; Av1 = Au1; Av2 = Au2; Av3 = Au3; Av4 = Au4; \
    Av5 = Au5; Av6 = Au6; Av7 = Au7; Av8 = Au8; Av9 = Au9; }

#define RELUN() \
    Hu0 = relu2(Au0); Hu1 = relu2(Au1); Hu2 = relu2(Au2); Hu3 = relu2(Au3); \
    Hu4 = relu2(Au4); Hu5 = relu2(Au5); Hu6 = relu2(Au6); Hu7 = relu2(Au7); \
    Hu8 = relu2(Au8); Hu9 = relu2(Au9); \
    Hv0 = relu2(Av0); Hv1 = relu2(Av1); Hv2 = relu2(Av2); Hv3 = relu2(Av3); \
    Hv4 = relu2(Av4); Hv5 = relu2(Av5); Hv6 = relu2(Av6); Hv7 = relu2(Av7); \
    Hv8 = relu2(Av8); Hv9 = relu2(Av9);

__global__ void __launch_bounds__(MAIN_THREADS, 2) main_kernel(
    const float* __restrict__ grad, const float* __restrict__ s0,
    const float* __restrict__ s1, const float* __restrict__ gp,
    const float* __restrict__ ex,
    const float* __restrict__ cw0, const float* __restrict__ cb0,
    const float* __restrict__ cw1, const float* __restrict__ cb1,
    const float* __restrict__ cw2, const float* __restrict__ cb2,
    const float* __restrict__ cw3, const float* __restrict__ cb3,
    float* __restrict__ out, int n) {
    // transposed natural rows: sw[c][j] = {w_out(2j), w_out(2j+1)}, 80 B/row
    __shared__ __align__(16) float2 sw0[4][10];
    __shared__ __align__(16) float2 sw1[20][10];
    __shared__ __align__(16) float2 sw2[20][10];
    __shared__ __align__(16) float2 sw3[10];
    __shared__ __align__(16) float2 sb0[10];
    __shared__ __align__(16) float2 sb1[10];
    __shared__ __align__(16) float2 sb2[10];
    __shared__ float sb3f;

    int tid = threadIdx.x;

    // ---- stage weights (transposed, natural pairs; coeff/fscale folded) ----
    if (tid < 40) {
        int c = tid / 10, j = tid % 10;
        float c0 = g_coeff0, c1 = g_coeff1, c2 = g_coeff2, c3 = g_coeff3;
        float cf = (c == 0) ? c0 : (c == 1) ? c1 : (c == 2) ? c2 : c3;
        sw0[c][j] = make_float2(cw0[(2 * j) * 4 + c] * cf,
                                cw0[(2 * j + 1) * 4 + c] * cf);
    }
    for (int k = tid; k < 200; k += MAIN_THREADS) {
        int c = k / 10, j = k % 10;
        sw1[c][j] = make_float2(cw1[(2 * j) * 20 + c], cw1[(2 * j + 1) * 20 + c]);
        sw2[c][j] = make_float2(cw2[(2 * j) * 20 + c], cw2[(2 * j + 1) * 20 + c]);
    }
    if (tid < 10) {
        sb0[tid] = make_float2(cb0[2 * tid], cb0[2 * tid + 1]);
        sb1[tid] = make_float2(cb1[2 * tid], cb1[2 * tid + 1]);
        sb2[tid] = make_float2(cb2[2 * tid], cb2[2 * tid + 1]);
        float fs = g_fscale;
        sw3[tid] = make_float2(cw3[2 * tid] * fs, cw3[2 * tid + 1] * fs);
    }
    if (tid == 0) sb3f = cb3[0] * g_fscale;
    __syncthreads();

    int p = blockIdx.x * MAIN_THREADS + tid;
    int npair = n >> 1;
    if (p >= npair) return;

    float inv_gn = g_inv_gn, inv_dn = g_inv_dn;

    float2 g2 = ((const float2*)grad)[p];
    float2 a2 = ((const float2*)s0)[p];
    float2 b2 = ((const float2*)s1)[p];
    float2 p2 = ((const float2*)gp)[p];
    float2 e2 = ((const float2*)ex)[p];

    float gxu = g2.x * inv_gn, gxv = g2.y * inv_gn;
    float dxu = (b2.x - a2.x) * inv_dn, dxv = (b2.y - a2.y) * inv_dn;

    u64 Au0, Au1, Au2, Au3, Au4, Au5, Au6, Au7, Au8, Au9;
    u64 Av0, Av1, Av2, Av3, Av4, Av5, Av6, Av7, Av8, Av9;
    u64 Hu0, Hu1, Hu2, Hu3, Hu4, Hu5, Hu6, Hu7, Hu8, Hu9;
    u64 Hv0, Hv1, Hv2, Hv3, Hv4, Hv5, Hv6, Hv7, Hv8, Hv9;

    // ---- layer 0: 4 -> 20 (coeff folded into sw0 rows) ----
    BIASN(sb0)
    {
        float t0u = p2.x * gxu, t0v = p2.y * gxv;  // gradient_param * g
        float t1u = e2.x * dxu, t1v = e2.y * dxv;  // extrapolation * d
        u64 du_ = pk(t0u, t0u), dv_ = pk(t0v, t0v);
        ACCROW2(&sw0[0][0], du_, dv_)
        du_ = pk(t1u, t1u); dv_ = pk(t1v, t1v);
        ACCROW2(&sw0[1][0], du_, dv_)
        du_ = pk(gxu, gxu); dv_ = pk(gxv, gxv);
        ACCROW2(&sw0[2][0], du_, dv_)
        du_ = pk(dxu, dxu); dv_ = pk(dxv, dxv);
        ACCROW2(&sw0[3][0], du_, dv_)
    }
    RELUN()

    // ---- layer 1: 20 -> 20 ----
    BIASN(sb1)
    LAYER20N(sw1)
    RELUN()

    // ---- layer 2: 20 -> 20 ----
    BIASN(sb2)
    LAYER20N(sw2)
    RELUN()

    // ---- layer 3: 20 -> 1: natural packed dot product (fscale folded) ----
    u64 acU = pk(sb3f, 0.0f);
    u64 acV = pk(sb3f, 0.0f);
    {
        const ulonglong2* r_ = (const ulonglong2*)sw3;
        ulonglong2 w0 = r_[0], w1 = r_[1], w2 = r_[2], w3 = r_[3], w4 = r_[4];
        acU = f2fma(w0.x, Hu0, acU); acV = f2fma(w0.x, Hv0, acV);
        acU = f2fma(w0.y, Hu1, acU); acV = f2fma(w0.y, Hv1, acV);
        acU = f2fma(w1.x, Hu2, acU); acV = f2fma(w1.x, Hv2, acV);
        acU = f2fma(w1.y, Hu3, acU); acV = f2fma(w1.y, Hv3, acV);
        acU = f2fma(w2.x, Hu4, acU); acV = f2fma(w2.x, Hv4, acV);
        acU = f2fma(w2.y, Hu5, acU); acV = f2fma(w2.y, Hv5, acV);
        acU = f2fma(w3.x, Hu6, acU); acV = f2fma(w3.x, Hv6, acV);
        acU = f2fma(w3.y, Hu7, acU); acV = f2fma(w3.y, Hv7, acV);
        acU = f2fma(w4.x, Hu8, acU); acV = f2fma(w4.x, Hv8, acV);
        acU = f2fma(w4.y, Hu9, acU); acV = f2fma(w4.y, Hv9, acV);
    }
    float2 ru = upk(acU), rv = upk(acV);
    float2 o2;
    o2.x = b2.x + (ru.x + ru.y);
    o2.y = b2.y + (rv.x + rv.y);
    ((float2*)out)[p] = o2;
}

// ---------------------------------------------------------------------------
extern "C" void kernel_launch(void* const* d_in, const int* in_sizes, int n_in,
                              void* d_out, int out_size) {
    const float* grad = (const float*)d_in[0];
    const float* s0   = (const float*)d_in[1];
    const float* s1   = (const float*)d_in[2];
    const float* loss_cur = (const float*)d_in[3];
    const float* loss_old = (const float*)d_in[4];
    const int*   iter_p   = (const int*)d_in[5];
    const float* gp = (const float*)d_in[6];
    const float* ex = (const float*)d_in[7];
    const float* cw0 = (const float*)d_in[8];
    const float* cb0 = (const float*)d_in[9];
    const float* cw1 = (const float*)d_in[10];
    const float* cb1 = (const float*)d_in[11];
    const float* cw2 = (const float*)d_in[12];
    const float* cb2 = (const float*)d_in[13];
    const float* cw3 = (const float*)d_in[14];
    const float* cb3 = (const float*)d_in[15];
    const float* lw0 = (const float*)d_in[16];
    const float* lb0 = (const float*)d_in[17];
    const float* lw1 = (const float*)d_in[18];
    const float* lb1 = (const float*)d_in[19];
    const float* lw2 = (const float*)d_in[20];
    const float* lb2 = (const float*)d_in[21];
    const float* lw3 = (const float*)d_in[22];
    const float* lb3 = (const float*)d_in[23];

    int n = in_sizes[0];
    int npair = n >> 1;
    int main_blocks = (npair + MAIN_THREADS - 1) / MAIN_THREADS;
    if (main_blocks < 1) main_blocks = 1;

    reduce_scalars_kernel<<<RED_BLOCKS, RED_THREADS>>>(
        grad, s0, s1, n, loss_cur, loss_old, iter_p,
        lw0, lb0, lw1, lb1, lw2, lb2, lw3, lb3);
    main_kernel<<<main_blocks, MAIN_THREADS>>>(grad, s0, s1, gp, ex,
                                               cw0, cb0, cw1, cb1, cw2, cb2,
                                               cw3, cb3, (float*)d_out, n);
}

// round 14
// speedup vs baseline: 1.4678x; 1.0005x over previous
#include <cuda_runtime.h>
#include <math.h>

// Learned optimizer step. Inputs (metadata order):
// 0 grad[N] 1 state0[N] 2 state1[N] 3 loss_cur[1] 4 loss_old[1] 5 iteration[1]
// 6 gradient_param[N] 7 extrapolation[N]
// 8 cw0[20x4] 9 cb0[20] 10 cw1[20x20] 11 cb1[20] 12 cw2[20x20] 13 cb2[20]
// 14 cw3[1x20] 15 cb3[1]
// 16 lw0[30x6] 17 lb0[30] 18 lw1[20x30] 19 lb1[20] 20 lw2[10x20] 21 lb2[10]
// 22 lw3[4x10] 23 lb3[4]
// Output: float32 [N]
//
// Main kernel: 4 elements/thread (u,v,w,x), FFMA2 with output-pair packed
// accumulators (R12 design). Every natural-pair weight quad now feeds FOUR
// elements -> per-pair LDS halves (240 -> 120 quads), pushing the L1 floor
// (~109us) far below the FFMA2 issue floor (~204us). Inputs/outputs move as
// LDG.128/STG.128. __launch_bounds__(128, 2): 255-reg budget, est ~210 live.

#define RED_BLOCKS 1024
#define RED_THREADS 256
#define MAIN_THREADS 128

typedef unsigned long long u64;

__device__ float4 g_part[RED_BLOCKS];
__device__ unsigned int g_ticket = 0;
__device__ float g_coeff0, g_coeff1, g_coeff2, g_coeff3;
__device__ float g_inv_gn;
__device__ float g_inv_dn;
__device__ float g_fscale;

// ---------- packed f32x2 helpers ----------
__device__ __forceinline__ u64 f2fma(u64 a, u64 b, u64 c) {
    u64 d;
    asm("fma.rn.f32x2 %0, %1, %2, %3;" : "=l"(d) : "l"(a), "l"(b), "l"(c));
    return d;
}
__device__ __forceinline__ u64 pk(float lo, float hi) {
    u64 r;
    asm("mov.b64 %0, {%1, %2};" : "=l"(r) : "f"(lo), "f"(hi));
    return r;
}
__device__ __forceinline__ float2 upk(u64 v) {
    float2 r;
    asm("mov.b64 {%0, %1}, %2;" : "=f"(r.x), "=f"(r.y) : "l"(v));
    return r;
}
__device__ __forceinline__ u64 relu2(u64 v) {
    float2 t = upk(v);
    return pk(fmaxf(t.x, 0.0f), fmaxf(t.y, 0.0f));
}

// ---------------------------------------------------------------------------
// Kernel A (fused): block partial reductions + last-block finalize
// ---------------------------------------------------------------------------
__global__ void reduce_scalars_kernel(
    const float* __restrict__ grad, const float* __restrict__ s0,
    const float* __restrict__ s1, int n,
    const float* __restrict__ loss_cur, const float* __restrict__ loss_old,
    const int* __restrict__ iter_p,
    const float* __restrict__ lw0, const float* __restrict__ lb0,
    const float* __restrict__ lw1, const float* __restrict__ lb1,
    const float* __restrict__ lw2, const float* __restrict__ lb2,
    const float* __restrict__ lw3, const float* __restrict__ lb3) {
    __shared__ float4 sh[RED_THREADS / 32];
    __shared__ int s_last;
    __shared__ float sfeat[6];
    __shared__ float sh0[30];
    __shared__ float sh1[20];
    __shared__ float sh2[10];

    int tid = threadIdx.x;
    int n4 = n >> 2;
    float sg2 = 0.f, sd2 = 0.f, sgd = 0.f, amax = 0.f;
    for (int i = blockIdx.x * blockDim.x + tid; i < n4;
         i += gridDim.x * blockDim.x) {
        float4 g = ((const float4*)grad)[i];
        float4 a = ((const float4*)s0)[i];
        float4 b = ((const float4*)s1)[i];
        float dx = b.x - a.x, dy = b.y - a.y, dz = b.z - a.z, dw = b.w - a.w;
        sg2 += g.x * g.x + g.y * g.y + g.z * g.z + g.w * g.w;
        sd2 += dx * dx + dy * dy + dz * dz + dw * dw;
        sgd += g.x * dx + g.y * dy + g.z * dz + g.w * dw;
        amax = fmaxf(amax, fmaxf(fmaxf(fabsf(g.x), fabsf(g.y)),
                                 fmaxf(fabsf(g.z), fabsf(g.w))));
    }
    #pragma unroll
    for (int off = 16; off; off >>= 1) {
        sg2 += __shfl_down_sync(0xffffffffu, sg2, off);
        sd2 += __shfl_down_sync(0xffffffffu, sd2, off);
        sgd += __shfl_down_sync(0xffffffffu, sgd, off);
        amax = fmaxf(amax, __shfl_down_sync(0xffffffffu, amax, off));
    }
    int lane = tid & 31, w = tid >> 5;
    if (!lane) sh[w] = make_float4(sg2, sd2, sgd, amax);
    __syncthreads();
    if (tid == 0) {
        float4 v = sh[0];
        #pragma unroll
        for (int i = 1; i < RED_THREADS / 32; i++) {
            float4 q = sh[i];
            v.x += q.x; v.y += q.y; v.z += q.z; v.w = fmaxf(v.w, q.w);
        }
        g_part[blockIdx.x] = v;
        __threadfence();
        unsigned int old = atomicInc(&g_ticket, RED_BLOCKS - 1);
        s_last = (old == RED_BLOCKS - 1);
    }
    __syncthreads();
    if (!s_last) return;

    sg2 = 0.f; sd2 = 0.f; sgd = 0.f; amax = 0.f;
    for (int i = tid; i < RED_BLOCKS; i += RED_THREADS) {
        float4 p = g_part[i];
        sg2 += p.x; sd2 += p.y; sgd += p.z; amax = fmaxf(amax, p.w);
    }
    #pragma unroll
    for (int off = 16; off; off >>= 1) {
        sg2 += __shfl_down_sync(0xffffffffu, sg2, off);
        sd2 += __shfl_down_sync(0xffffffffu, sd2, off);
        sgd += __shfl_down_sync(0xffffffffu, sgd, off);
        amax = fmaxf(amax, __shfl_down_sync(0xffffffffu, amax, off));
    }
    __syncthreads();
    if (!lane) sh[w] = make_float4(sg2, sd2, sgd, amax);
    __syncthreads();

    if (tid == 0) {
        float4 v = sh[0];
        #pragma unroll
        for (int i = 1; i < RED_THREADS / 32; i++) {
            float4 q = sh[i];
            v.x += q.x; v.y += q.y; v.z += q.z; v.w = fmaxf(v.w, q.w);
        }
        float gn = sqrtf(v.x);
        float dn = sqrtf(v.y);
        float inv_gn = (gn > 1e-10f) ? (1.0f / gn) : 1.0f;
        float inv_dn = (dn > 1e-10f) ? (1.0f / dn) : 1.0f;
        float it = (float)iter_p[0];
        sfeat[0] = log1pf(gn);
        sfeat[1] = log1pf(dn);
        sfeat[2] = v.z * inv_gn * inv_dn;
        sfeat[3] = v.w * inv_gn;
        sfeat[4] = it;
        sfeat[5] = logf(loss_cur[0]) - logf(loss_old[0]);
        g_inv_gn = inv_gn;
        g_inv_dn = inv_dn;
        g_fscale = 1.0f / sqrtf(1.0f + it);
    }
    __syncthreads();

    if (tid < 30) {
        float a = lb0[tid];
        #pragma unroll
        for (int f = 0; f < 6; f++) a = fmaf(lw0[tid * 6 + f], sfeat[f], a);
        sh0[tid] = fmaxf(a, 0.0f);
    }
    __syncthreads();
    if (tid < 20) {
        float a = lb1[tid];
        #pragma unroll
        for (int c = 0; c < 30; c++) a = fmaf(lw1[tid * 30 + c], sh0[c], a);
        sh1[tid] = fmaxf(a, 0.0f);
    }
    __syncthreads();
    if (tid < 10) {
        float a = lb2[tid];
        #pragma unroll
        for (int c = 0; c < 20; c++) a = fmaf(lw2[tid * 20 + c], sh1[c], a);
        sh2[tid] = fmaxf(a, 0.0f);
    }
    __syncthreads();
    if (tid < 4) {
        float a = lb3[tid];
        #pragma unroll
        for (int c = 0; c < 10; c++) a = fmaf(lw3[tid * 10 + c], sh2[c], a);
        if (tid == 0) g_coeff0 = a;
        if (tid == 1) g_coeff1 = a;
        if (tid == 2) g_coeff2 = a;
        if (tid == 3) g_coeff3 = a;
    }
}

// ---------------------------------------------------------------------------
// Kernel B: per-element MLP 4->20->20->20->1, 4 elements/thread (u,v,w,x).
// Output-pair packed accumulators; natural-pair weight rows shared by all 4.
// ---------------------------------------------------------------------------

// All 10 output-pairs of all 4 elems += natural weight row * dups
#define ACCROW4(ROWPTR, DU, DV, DW, DX) { \
    const ulonglong2* r_ = (const ulonglong2*)(ROWPTR); \
    ulonglong2 q0 = r_[0], q1 = r_[1], q2 = r_[2], q3 = r_[3], q4 = r_[4]; \
    Au0 = f2fma(q0.x, (DU), Au0); Av0 = f2fma(q0.x, (DV), Av0); \
    Aw0 = f2fma(q0.x, (DW), Aw0); Ax0 = f2fma(q0.x, (DX), Ax0); \
    Au1 = f2fma(q0.y, (DU), Au1); Av1 = f2fma(q0.y, (DV), Av1); \
    Aw1 = f2fma(q0.y, (DW), Aw1); Ax1 = f2fma(q0.y, (DX), Ax1); \
    Au2 = f2fma(q1.x, (DU), Au2); Av2 = f2fma(q1.x, (DV), Av2); \
    Aw2 = f2fma(q1.x, (DW), Aw2); Ax2 = f2fma(q1.x, (DX), Ax2); \
    Au3 = f2fma(q1.y, (DU), Au3); Av3 = f2fma(q1.y, (DV), Av3); \
    Aw3 = f2fma(q1.y, (DW), Aw3); Ax3 = f2fma(q1.y, (DX), Ax3); \
    Au4 = f2fma(q2.x, (DU), Au4); Av4 = f2fma(q2.x, (DV), Av4); \
    Aw4 = f2fma(q2.x, (DW), Aw4); Ax4 = f2fma(q2.x, (DX), Ax4); \
    Au5 = f2fma(q2.y, (DU), Au5); Av5 = f2fma(q2.y, (DV), Av5); \
    Aw5 = f2fma(q2.y, (DW), Aw5); Ax5 = f2fma(q2.y, (DX), Ax5); \
    Au6 = f2fma(q3.x, (DU), Au6); Av6 = f2fma(q3.x, (DV), Av6); \
    Aw6 = f2fma(q3.x, (DW), Aw6); Ax6 = f2fma(q3.x, (DX), Ax6); \
    Au7 = f2fma(q3.y, (DU), Au7); Av7 = f2fma(q3.y, (DV), Av7); \
    Aw7 = f2fma(q3.y, (DW), Aw7); Ax7 = f2fma(q3.y, (DX), Ax7); \
    Au8 = f2fma(q4.x, (DU), Au8); Av8 = f2fma(q4.x, (DV), Av8); \
    Aw8 = f2fma(q4.x, (DW), Aw8); Ax8 = f2fma(q4.x, (DX), Ax8); \
    Au9 = f2fma(q4.y, (DU), Au9); Av9 = f2fma(q4.y, (DV), Av9); \
    Aw9 = f2fma(q4.y, (DW), Aw9); Ax9 = f2fma(q4.y, (DX), Ax9); }

// Channels 2K and 2K+1: extract scalars from H pair K of each elem, dup, acc.
#define CH4(SW, K) { \
    float2 hu_ = upk(Hu##K); float2 hv_ = upk(Hv##K); \
    float2 hw_ = upk(Hw##K); float2 hx_ = upk(Hx##K); \
    u64 du_ = pk(hu_.x, hu_.x); u64 dv_ = pk(hv_.x, hv_.x); \
    u64 dw_ = pk(hw_.x, hw_.x); u64 dx_ = pk(hx_.x, hx_.x); \
    ACCROW4(&(SW)[2 * (K)][0], du_, dv_, dw_, dx_); \
    du_ = pk(hu_.y, hu_.y); dv_ = pk(hv_.y, hv_.y); \
    dw_ = pk(hw_.y, hw_.y); dx_ = pk(hx_.y, hx_.y); \
    ACCROW4(&(SW)[2 * (K) + 1][0], du_, dv_, dw_, dx_); }

#define LAYER20N4(SW) \
    CH4(SW, 0) CH4(SW, 1) CH4(SW, 2) CH4(SW, 3) CH4(SW, 4) \
    CH4(SW, 5) CH4(SW, 6) CH4(SW, 7) CH4(SW, 8) CH4(SW, 9)

#define BIASN4(SB) { \
    const ulonglong2* b_ = (const ulonglong2*)(SB); \
    ulonglong2 q0 = b_[0], q1 = b_[1], q2 = b_[2], q3 = b_[3], q4 = b_[4]; \
    Au0 = q0.x; Au1 = q0.y; Au2 = q1.x; Au3 = q1.y; Au4 = q2.x; \
    Au5 = q2.y; Au6 = q3.x; Au7 = q3.y; Au8 = q4.x; Au9 = q4.y; \
    Av0 = Au0; Av1 = Au1; Av2 = Au2; Av3 = Au3; Av4 = Au4; \
    Av5 = Au5; Av6 = Au6; Av7 = Au7; Av8 = Au8; Av9 = Au9; \
    Aw0 = Au0; Aw1 = Au1; Aw2 = Au2; Aw3 = Au3; Aw4 = Au4; \
    Aw5 = Au5; Aw6 = Au6; Aw7 = Au7; Aw8 = Au8; Aw9 = Au9; \
    Ax0 = Au0; Ax1 = Au1; Ax2 = Au2; Ax3 = Au3; Ax4 = Au4; \
    Ax5 = Au5; Ax6 = Au6; Ax7 = Au7; Ax8 = Au8; Ax9 = Au9; }

#define RELUN4() \
    Hu0 = relu2(Au0); Hu1 = relu2(Au1); Hu2 = relu2(Au2); Hu3 = relu2(Au3); \
    Hu4 = relu2(Au4); Hu5 = relu2(Au5); Hu6 = relu2(Au6); Hu7 = relu2(Au7); \
    Hu8 = relu2(Au8); Hu9 = relu2(Au9); \
    Hv0 = relu2(Av0); Hv1 = relu2(Av1); Hv2 = relu2(Av2); Hv3 = relu2(Av3); \
    Hv4 = relu2(Av4); Hv5 = relu2(Av5); Hv6 = relu2(Av6); Hv7 = relu2(Av7); \
    Hv8 = relu2(Av8); Hv9 = relu2(Av9); \
    Hw0 = relu2(Aw0); Hw1 = relu2(Aw1); Hw2 = relu2(Aw2); Hw3 = relu2(Aw3); \
    Hw4 = relu2(Aw4); Hw5 = relu2(Aw5); Hw6 = relu2(Aw6); Hw7 = relu2(Aw7); \
    Hw8 = relu2(Aw8); Hw9 = relu2(Aw9); \
    Hx0 = relu2(Ax0); Hx1 = relu2(Ax1); Hx2 = relu2(Ax2); Hx3 = relu2(Ax3); \
    Hx4 = relu2(Ax4); Hx5 = relu2(Ax5); Hx6 = relu2(Ax6); Hx7 = relu2(Ax7); \
    Hx8 = relu2(Ax8); Hx9 = relu2(Ax9);

#define DECL10(P) \
    u64 P##0, P##1, P##2, P##3, P##4, P##5, P##6, P##7, P##8, P##9;

__global__ void __launch_bounds__(MAIN_THREADS, 2) main_kernel(
    const float* __restrict__ grad, const float* __restrict__ s0,
    const float* __restrict__ s1, const float* __restrict__ gp,
    const float* __restrict__ ex,
    const float* __restrict__ cw0, const float* __restrict__ cb0,
    const float* __restrict__ cw1, const float* __restrict__ cb1,
    const float* __restrict__ cw2, const float* __restrict__ cb2,
    const float* __restrict__ cw3, const float* __restrict__ cb3,
    float* __restrict__ out, int n) {
    // transposed natural rows: sw[c][j] = {w_out(2j), w_out(2j+1)}, 80 B/row
    __shared__ __align__(16) float2 sw0[4][10];
    __shared__ __align__(16) float2 sw1[20][10];
    __shared__ __align__(16) float2 sw2[20][10];
    __shared__ __align__(16) float2 sw3[10];
    __shared__ __align__(16) float2 sb0[10];
    __shared__ __align__(16) float2 sb1[10];
    __shared__ __align__(16) float2 sb2[10];
    __shared__ float sb3f;

    int tid = threadIdx.x;

    // ---- stage weights (transposed, natural pairs; coeff/fscale folded) ----
    if (tid < 40) {
        int c = tid / 10, j = tid % 10;
        float c0 = g_coeff0, c1 = g_coeff1, c2 = g_coeff2, c3 = g_coeff3;
        float cf = (c == 0) ? c0 : (c == 1) ? c1 : (c == 2) ? c2 : c3;
        sw0[c][j] = make_float2(cw0[(2 * j) * 4 + c] * cf,
                                cw0[(2 * j + 1) * 4 + c] * cf);
    }
    for (int k = tid; k < 200; k += MAIN_THREADS) {
        int c = k / 10, j = k % 10;
        sw1[c][j] = make_float2(cw1[(2 * j) * 20 + c], cw1[(2 * j + 1) * 20 + c]);
        sw2[c][j] = make_float2(cw2[(2 * j) * 20 + c], cw2[(2 * j + 1) * 20 + c]);
    }
    if (tid < 10) {
        sb0[tid] = make_float2(cb0[2 * tid], cb0[2 * tid + 1]);
        sb1[tid] = make_float2(cb1[2 * tid], cb1[2 * tid + 1]);
        sb2[tid] = make_float2(cb2[2 * tid], cb2[2 * tid + 1]);
        float fs = g_fscale;
        sw3[tid] = make_float2(cw3[2 * tid] * fs, cw3[2 * tid + 1] * fs);
    }
    if (tid == 0) sb3f = cb3[0] * g_fscale;
    __syncthreads();

    int i = blockIdx.x * MAIN_THREADS + tid;   // index into float4 arrays
    int nq = n >> 2;
    if (i >= nq) return;

    float inv_gn = g_inv_gn, inv_dn = g_inv_dn;

    float4 g4 = ((const float4*)grad)[i];
    float4 a4 = ((const float4*)s0)[i];
    float4 b4 = ((const float4*)s1)[i];
    float4 p4 = ((const float4*)gp)[i];
    float4 e4 = ((const float4*)ex)[i];

    float gxu = g4.x * inv_gn, gxv = g4.y * inv_gn;
    float gxw = g4.z * inv_gn, gxx = g4.w * inv_gn;
    float dxu = (b4.x - a4.x) * inv_dn, dxv = (b4.y - a4.y) * inv_dn;
    float dxw = (b4.z - a4.z) * inv_dn, dxx = (b4.w - a4.w) * inv_dn;

    DECL10(Au) DECL10(Av) DECL10(Aw) DECL10(Ax)
    DECL10(Hu) DECL10(Hv) DECL10(Hw) DECL10(Hx)

    // ---- layer 0: 4 -> 20 (coeff folded into sw0 rows) ----
    BIASN4(sb0)
    {
        u64 du_ = pk(p4.x * gxu, p4.x * gxu), dv_ = pk(p4.y * gxv, p4.y * gxv);
        u64 dw_ = pk(p4.z * gxw, p4.z * gxw), dx_ = pk(p4.w * gxx, p4.w * gxx);
        ACCROW4(&sw0[0][0], du_, dv_, dw_, dx_)
        du_ = pk(e4.x * dxu, e4.x * dxu); dv_ = pk(e4.y * dxv, e4.y * dxv);
        dw_ = pk(e4.z * dxw, e4.z * dxw); dx_ = pk(e4.w * dxx, e4.w * dxx);
        ACCROW4(&sw0[1][0], du_, dv_, dw_, dx_)
        du_ = pk(gxu, gxu); dv_ = pk(gxv, gxv);
        dw_ = pk(gxw, gxw); dx_ = pk(gxx, gxx);
        ACCROW4(&sw0[2][0], du_, dv_, dw_, dx_)
        du_ = pk(dxu, dxu); dv_ = pk(dxv, dxv);
        dw_ = pk(dxw, dxw); dx_ = pk(dxx, dxx);
        ACCROW4(&sw0[3][0], du_, dv_, dw_, dx_)
    }
    RELUN4()

    // ---- layer 1: 20 -> 20 ----
    BIASN4(sb1)
    LAYER20N4(sw1)
    RELUN4()

    // ---- layer 2: 20 -> 20 ----
    BIASN4(sb2)
    LAYER20N4(sw2)
    RELUN4()

    // ---- layer 3: 20 -> 1: natural packed dot products (fscale folded) ----
    u64 acU = pk(sb3f, 0.0f);
    u64 acV = pk(sb3f, 0.0f);
    u64 acW = pk(sb3f, 0.0f);
    u64 acX = pk(sb3f, 0.0f);
    {
        const ulonglong2* r_ = (const ulonglong2*)sw3;
        ulonglong2 q0 = r_[0], q1 = r_[1], q2 = r_[2], q3 = r_[3], q4 = r_[4];
        acU = f2fma(q0.x, Hu0, acU); acV = f2fma(q0.x, Hv0, acV);
        acW = f2fma(q0.x, Hw0, acW); acX = f2fma(q0.x, Hx0, acX);
        acU = f2fma(q0.y, Hu1, acU); acV = f2fma(q0.y, Hv1, acV);
        acW = f2fma(q0.y, Hw1, acW); acX = f2fma(q0.y, Hx1, acX);
        acU = f2fma(q1.x, Hu2, acU); acV = f2fma(q1.x, Hv2, acV);
        acW = f2fma(q1.x, Hw2, acW); acX = f2fma(q1.x, Hx2, acX);
        acU = f2fma(q1.y, Hu3, acU); acV = f2fma(q1.y, Hv3, acV);
        acW = f2fma(q1.y, Hw3, acW); acX = f2fma(q1.y, Hx3, acX);
        acU = f2fma(q2.x, Hu4, acU); acV = f2fma(q2.x, Hv4, acV);
        acW = f2fma(q2.x, Hw4, acW); acX = f2fma(q2.x, Hx4, acX);
        acU = f2fma(q2.y, Hu5, acU); acV = f2fma(q2.y, Hv5, acV);
        acW = f2fma(q2.y, Hw5, acW); acX = f2fma(q2.y, Hx5, acX);
        acU = f2fma(q3.x, Hu6, acU); acV = f2fma(q3.x, Hv6, acV);
        acW = f2fma(q3.x, Hw6, acW); acX = f2fma(q3.x, Hx6, acX);
        acU = f2fma(q3.y, Hu7, acU); acV = f2fma(q3.y, Hv7, acV);
        acW = f2fma(q3.y, Hw7, acW); acX = f2fma(q3.y, Hx7, acX);
        acU = f2fma(q4.x, Hu8, acU); acV = f2fma(q4.x, Hv8, acV);
        acW = f2fma(q4.x, Hw8, acW); acX = f2fma(q4.x, Hx8, acX);
        acU = f2fma(q4.y, Hu9, acU); acV = f2fma(q4.y, Hv9, acV);
        acW = f2fma(q4.y, Hw9, acW); acX = f2fma(q4.y, Hx9, acX);
    }
    float2 ru = upk(acU), rv = upk(acV), rw = upk(acW), rx = upk(acX);
    float4 o4;
    o4.x = b4.x + (ru.x + ru.y);
    o4.y = b4.y + (rv.x + rv.y);
    o4.z = b4.z + (rw.x + rw.y);
    o4.w = b4.w + (rx.x + rx.y);
    ((float4*)out)[i] = o4;
}

// ---------------------------------------------------------------------------
extern "C" void kernel_launch(void* const* d_in, const int* in_sizes, int n_in,
                              void* d_out, int out_size) {
    const float* grad = (const float*)d_in[0];
    const float* s0   = (const float*)d_in[1];
    const float* s1   = (const float*)d_in[2];
    const float* loss_cur = (const float*)d_in[3];
    const float* loss_old = (const float*)d_in[4];
    const int*   iter_p   = (const int*)d_in[5];
    const float* gp = (const float*)d_in[6];
    const float* ex = (const float*)d_in[7];
    const float* cw0 = (const float*)d_in[8];
    const float* cb0 = (const float*)d_in[9];
    const float* cw1 = (const float*)d_in[10];
    const float* cb1 = (const float*)d_in[11];
    const float* cw2 = (const float*)d_in[12];
    const float* cb2 = (const float*)d_in[13];
    const float* cw3 = (const float*)d_in[14];
    const float* cb3 = (const float*)d_in[15];
    const float* lw0 = (const float*)d_in[16];
    const float* lb0 = (const float*)d_in[17];
    const float* lw1 = (const float*)d_in[18];
    const float* lb1 = (const float*)d_in[19];
    const float* lw2 = (const float*)d_in[20];
    const float* lb2 = (const float*)d_in[21];
    const float* lw3 = (const float*)d_in[22];
    const float* lb3 = (const float*)d_in[23];

    int n = in_sizes[0];
    int nq = n >> 2;
    int main_blocks = (nq + MAIN_THREADS - 1) / MAIN_THREADS;
    if (main_blocks < 1) main_blocks = 1;

    reduce_scalars_kernel<<<RED_BLOCKS, RED_THREADS>>>(
        grad, s0, s1, n, loss_cur, loss_old, iter_p,
        lw0, lb0, lw1, lb1, lw2, lb2, lw3, lb3);
    main_kernel<<<main_blocks, MAIN_THREADS>>>(grad, s0, s1, gp, ex,
                                               cw0, cb0, cw1, cb1, cw2, cb2,
                                               cw3, cb3, (float*)d_out, n);
}

// round 17
// speedup vs baseline: 1.8051x; 1.2298x over previous
#include <cuda_runtime.h>
#include <cuda_fp16.h>
#include <math.h>
#include <string.h>

// Learned optimizer step. Inputs (metadata order):
// 0 grad[N] 1 state0[N] 2 state1[N] 3 loss_cur[1] 4 loss_old[1] 5 iteration[1]
// 6 gradient_param[N] 7 extrapolation[N]
// 8 cw0[20x4] 9 cb0[20] 10 cw1[20x20] 11 cb1[20] 12 cw2[20x20] 13 cb2[20]
// 14 cw3[1x20] 15 cb3[1]
// 16 lw0[30x6] 17 lb0[30] 18 lw1[20x30] 19 lb1[20] 20 lw2[10x20] 21 lb2[10]
// 22 lw3[4x10] 23 lb3[4]
// Output: float32 [N]
//
// R14 finding: FFMA2 with 3 register-pair operands hits the RF-bank limit
// (3 even + 3 odd distinct regs -> rt=3), capping fma at 2/3 of peak — both
// R12 and R14 measured exactly that. This round: layers 1/2/3 in HFMA2
// (three single-reg operands -> rt=2, same 2-FMA density). Layer 0 stays
// fp32 FFMA2 (its inputs are ~1e-7 — fp16 subnormal territory); its outputs
// (~0.01..1) convert cleanly to half2. Final dot -> f32, +cb3, *fscale, +s1.

#define RED_BLOCKS 1024
#define RED_THREADS 256
#define MAIN_THREADS 128

typedef unsigned long long u64;

__device__ float4 g_part[RED_BLOCKS];
__device__ unsigned int g_ticket = 0;
__device__ float g_coeff0, g_coeff1, g_coeff2, g_coeff3;
__device__ float g_inv_gn;
__device__ float g_inv_dn;
__device__ float g_fscale;

// ---------- packed f32x2 helpers ----------
__device__ __forceinline__ u64 f2fma(u64 a, u64 b, u64 c) {
    u64 d;
    asm("fma.rn.f32x2 %0, %1, %2, %3;" : "=l"(d) : "l"(a), "l"(b), "l"(c));
    return d;
}
__device__ __forceinline__ u64 pk(float lo, float hi) {
    u64 r;
    asm("mov.b64 %0, {%1, %2};" : "=l"(r) : "f"(lo), "f"(hi));
    return r;
}
__device__ __forceinline__ float2 upk(u64 v) {
    float2 r;
    asm("mov.b64 {%0, %1}, %2;" : "=f"(r.x), "=f"(r.y) : "l"(v));
    return r;
}
__device__ __forceinline__ __half2 u2h(unsigned int u) {
    __half2 h;
    memcpy(&h, &u, 4);
    return h;
}
// relu in f32 then convert the pair to half2 {lo, hi}
__device__ __forceinline__ __half2 relucvt(u64 v) {
    float2 f = upk(v);
    return __floats2half2_rn(fmaxf(f.x, 0.0f), fmaxf(f.y, 0.0f));
}

// ---------------------------------------------------------------------------
// Kernel A (fused): block partial reductions + last-block finalize
// ---------------------------------------------------------------------------
__global__ void reduce_scalars_kernel(
    const float* __restrict__ grad, const float* __restrict__ s0,
    const float* __restrict__ s1, int n,
    const float* __restrict__ loss_cur, const float* __restrict__ loss_old,
    const int* __restrict__ iter_p,
    const float* __restrict__ lw0, const float* __restrict__ lb0,
    const float* __restrict__ lw1, const float* __restrict__ lb1,
    const float* __restrict__ lw2, const float* __restrict__ lb2,
    const float* __restrict__ lw3, const float* __restrict__ lb3) {
    __shared__ float4 sh[RED_THREADS / 32];
    __shared__ int s_last;
    __shared__ float sfeat[6];
    __shared__ float sh0[30];
    __shared__ float sh1[20];
    __shared__ float sh2[10];

    int tid = threadIdx.x;
    int n4 = n >> 2;
    float sg2 = 0.f, sd2 = 0.f, sgd = 0.f, amax = 0.f;
    for (int i = blockIdx.x * blockDim.x + tid; i < n4;
         i += gridDim.x * blockDim.x) {
        float4 g = ((const float4*)grad)[i];
        float4 a = ((const float4*)s0)[i];
        float4 b = ((const float4*)s1)[i];
        float dx = b.x - a.x, dy = b.y - a.y, dz = b.z - a.z, dw = b.w - a.w;
        sg2 += g.x * g.x + g.y * g.y + g.z * g.z + g.w * g.w;
        sd2 += dx * dx + dy * dy + dz * dz + dw * dw;
        sgd += g.x * dx + g.y * dy + g.z * dz + g.w * dw;
        amax = fmaxf(amax, fmaxf(fmaxf(fabsf(g.x), fabsf(g.y)),
                                 fmaxf(fabsf(g.z), fabsf(g.w))));
    }
    #pragma unroll
    for (int off = 16; off; off >>= 1) {
        sg2 += __shfl_down_sync(0xffffffffu, sg2, off);
        sd2 += __shfl_down_sync(0xffffffffu, sd2, off);
        sgd += __shfl_down_sync(0xffffffffu, sgd, off);
        amax = fmaxf(amax, __shfl_down_sync(0xffffffffu, amax, off));
    }
    int lane = tid & 31, w = tid >> 5;
    if (!lane) sh[w] = make_float4(sg2, sd2, sgd, amax);
    __syncthreads();
    if (tid == 0) {
        float4 v = sh[0];
        #pragma unroll
        for (int i = 1; i < RED_THREADS / 32; i++) {
            float4 q = sh[i];
            v.x += q.x; v.y += q.y; v.z += q.z; v.w = fmaxf(v.w, q.w);
        }
        g_part[blockIdx.x] = v;
        __threadfence();
        unsigned int old = atomicInc(&g_ticket, RED_BLOCKS - 1);
        s_last = (old == RED_BLOCKS - 1);
    }
    __syncthreads();
    if (!s_last) return;

    sg2 = 0.f; sd2 = 0.f; sgd = 0.f; amax = 0.f;
    for (int i = tid; i < RED_BLOCKS; i += RED_THREADS) {
        float4 p = g_part[i];
        sg2 += p.x; sd2 += p.y; sgd += p.z; amax = fmaxf(amax, p.w);
    }
    #pragma unroll
    for (int off = 16; off; off >>= 1) {
        sg2 += __shfl_down_sync(0xffffffffu, sg2, off);
        sd2 += __shfl_down_sync(0xffffffffu, sd2, off);
        sgd += __shfl_down_sync(0xffffffffu, sgd, off);
        amax = fmaxf(amax, __shfl_down_sync(0xffffffffu, amax, off));
    }
    __syncthreads();
    if (!lane) sh[w] = make_float4(sg2, sd2, sgd, amax);
    __syncthreads();

    if (tid == 0) {
        float4 v = sh[0];
        #pragma unroll
        for (int i = 1; i < RED_THREADS / 32; i++) {
            float4 q = sh[i];
            v.x += q.x; v.y += q.y; v.z += q.z; v.w = fmaxf(v.w, q.w);
        }
        float gn = sqrtf(v.x);
        float dn = sqrtf(v.y);
        float inv_gn = (gn > 1e-10f) ? (1.0f / gn) : 1.0f;
        float inv_dn = (dn > 1e-10f) ? (1.0f / dn) : 1.0f;
        float it = (float)iter_p[0];
        sfeat[0] = log1pf(gn);
        sfeat[1] = log1pf(dn);
        sfeat[2] = v.z * inv_gn * inv_dn;
        sfeat[3] = v.w * inv_gn;
        sfeat[4] = it;
        sfeat[5] = logf(loss_cur[0]) - logf(loss_old[0]);
        g_inv_gn = inv_gn;
        g_inv_dn = inv_dn;
        g_fscale = 1.0f / sqrtf(1.0f + it);
    }
    __syncthreads();

    if (tid < 30) {
        float a = lb0[tid];
        #pragma unroll
        for (int f = 0; f < 6; f++) a = fmaf(lw0[tid * 6 + f], sfeat[f], a);
        sh0[tid] = fmaxf(a, 0.0f);
    }
    __syncthreads();
    if (tid < 20) {
        float a = lb1[tid];
        #pragma unroll
        for (int c = 0; c < 30; c++) a = fmaf(lw1[tid * 30 + c], sh0[c], a);
        sh1[tid] = fmaxf(a, 0.0f);
    }
    __syncthreads();
    if (tid < 10) {
        float a = lb2[tid];
        #pragma unroll
        for (int c = 0; c < 20; c++) a = fmaf(lw2[tid * 20 + c], sh1[c], a);
        sh2[tid] = fmaxf(a, 0.0f);
    }
    __syncthreads();
    if (tid < 4) {
        float a = lb3[tid];
        #pragma unroll
        for (int c = 0; c < 10; c++) a = fmaf(lw3[tid * 10 + c], sh2[c], a);
        if (tid == 0) g_coeff0 = a;
        if (tid == 1) g_coeff1 = a;
        if (tid == 2) g_coeff2 = a;
        if (tid == 3) g_coeff3 = a;
    }
}

// ---------------------------------------------------------------------------
// Kernel B: 4 elements/thread (u,v,w,x).
// Layer 0: fp32 FFMA2, two 10-output halves (5 output-pairs/elem live).
// Layers 1,2,3: fp16 HFMA2, output-pair packed half2 accumulators,
// natural-pair half2 weight rows (48 B padded -> 3 LDS.128 per channel).
// ---------------------------------------------------------------------------

// ---- fp32 layer-0 half: 5 output-pairs per elem ----
#define ACC5(ROWPTR, DU, DV, DW, DX) { \
    const ulonglong2* r_ = (const ulonglong2*)(ROWPTR); \
    ulonglong2 q0 = r_[0], q1 = r_[1]; \
    u64 w4_ = ((const u64*)(ROWPTR))[4]; \
    Pu0 = f2fma(q0.x, (DU), Pu0); Pv0 = f2fma(q0.x, (DV), Pv0); \
    Pw0 = f2fma(q0.x, (DW), Pw0); Px0 = f2fma(q0.x, (DX), Px0); \
    Pu1 = f2fma(q0.y, (DU), Pu1); Pv1 = f2fma(q0.y, (DV), Pv1); \
    Pw1 = f2fma(q0.y, (DW), Pw1); Px1 = f2fma(q0.y, (DX), Px1); \
    Pu2 = f2fma(q1.x, (DU), Pu2); Pv2 = f2fma(q1.x, (DV), Pv2); \
    Pw2 = f2fma(q1.x, (DW), Pw2); Px2 = f2fma(q1.x, (DX), Px2); \
    Pu3 = f2fma(q1.y, (DU), Pu3); Pv3 = f2fma(q1.y, (DV), Pv3); \
    Pw3 = f2fma(q1.y, (DW), Pw3); Px3 = f2fma(q1.y, (DX), Px3); \
    Pu4 = f2fma(w4_, (DU), Pu4); Pv4 = f2fma(w4_, (DV), Pv4); \
    Pw4 = f2fma(w4_, (DW), Pw4); Px4 = f2fma(w4_, (DX), Px4); }

#define BIAS5(SB) { \
    const ulonglong2* b_ = (const ulonglong2*)(SB); \
    ulonglong2 q0 = b_[0], q1 = b_[1]; \
    u64 b4_ = ((const u64*)(SB))[4]; \
    Pu0 = q0.x; Pu1 = q0.y; Pu2 = q1.x; Pu3 = q1.y; Pu4 = b4_; \
    Pv0 = Pu0; Pv1 = Pu1; Pv2 = Pu2; Pv3 = Pu3; Pv4 = Pu4; \
    Pw0 = Pu0; Pw1 = Pu1; Pw2 = Pu2; Pw3 = Pu3; Pw4 = Pu4; \
    Px0 = Pu0; Px1 = Pu1; Px2 = Pu2; Px3 = Pu3; Px4 = Pu4; }

#define CVTHALF(BASE) \
    Hhu##BASE##0 = relucvt(Pu0); Hhu##BASE##1 = relucvt(Pu1); \
    Hhu##BASE##2 = relucvt(Pu2); Hhu##BASE##3 = relucvt(Pu3); \
    Hhu##BASE##4 = relucvt(Pu4); \
    Hhv##BASE##0 = relucvt(Pv0); Hhv##BASE##1 = relucvt(Pv1); \
    Hhv##BASE##2 = relucvt(Pv2); Hhv##BASE##3 = relucvt(Pv3); \
    Hhv##BASE##4 = relucvt(Pv4); \
    Hhw##BASE##0 = relucvt(Pw0); Hhw##BASE##1 = relucvt(Pw1); \
    Hhw##BASE##2 = relucvt(Pw2); Hhw##BASE##3 = relucvt(Pw3); \
    Hhw##BASE##4 = relucvt(Pw4); \
    Hhx##BASE##0 = relucvt(Px0); Hhx##BASE##1 = relucvt(Px1); \
    Hhx##BASE##2 = relucvt(Px2); Hhx##BASE##3 = relucvt(Px3); \
    Hhx##BASE##4 = relucvt(Px4);

// ---- fp16 layer machinery ----
// All 10 output-pairs of all 4 elems += natural half2 weight row * dups
#define HACCROW4(ROWPTR, DU, DV, DW, DX) { \
    const uint4* r_ = (const uint4*)(ROWPTR); \
    uint4 q0 = r_[0], q1 = r_[1], q2 = r_[2]; \
    __half2 h0_ = u2h(q0.x), h1_ = u2h(q0.y), h2_ = u2h(q0.z), h3_ = u2h(q0.w); \
    __half2 h4_ = u2h(q1.x), h5_ = u2h(q1.y), h6_ = u2h(q1.z), h7_ = u2h(q1.w); \
    __half2 h8_ = u2h(q2.x), h9_ = u2h(q2.y); \
    Ku0 = __hfma2(h0_, (DU), Ku0); Kv0 = __hfma2(h0_, (DV), Kv0); \
    Kw0 = __hfma2(h0_, (DW), Kw0); Kx0 = __hfma2(h0_, (DX), Kx0); \
    Ku1 = __hfma2(h1_, (DU), Ku1); Kv1 = __hfma2(h1_, (DV), Kv1); \
    Kw1 = __hfma2(h1_, (DW), Kw1); Kx1 = __hfma2(h1_, (DX), Kx1); \
    Ku2 = __hfma2(h2_, (DU), Ku2); Kv2 = __hfma2(h2_, (DV), Kv2); \
    Kw2 = __hfma2(h2_, (DW), Kw2); Kx2 = __hfma2(h2_, (DX), Kx2); \
    Ku3 = __hfma2(h3_, (DU), Ku3); Kv3 = __hfma2(h3_, (DV), Kv3); \
    Kw3 = __hfma2(h3_, (DW), Kw3); Kx3 = __hfma2(h3_, (DX), Kx3); \
    Ku4 = __hfma2(h4_, (DU), Ku4); Kv4 = __hfma2(h4_, (DV), Kv4); \
    Kw4 = __hfma2(h4_, (DW), Kw4); Kx4 = __hfma2(h4_, (DX), Kx4); \
    Ku5 = __hfma2(h5_, (DU), Ku5); Kv5 = __hfma2(h5_, (DV), Kv5); \
    Kw5 = __hfma2(h5_, (DW), Kw5); Kx5 = __hfma2(h5_, (DX), Kx5); \
    Ku6 = __hfma2(h6_, (DU), Ku6); Kv6 = __hfma2(h6_, (DV), Kv6); \
    Kw6 = __hfma2(h6_, (DW), Kw6); Kx6 = __hfma2(h6_, (DX), Kx6); \
    Ku7 = __hfma2(h7_, (DU), Ku7); Kv7 = __hfma2(h7_, (DV), Kv7); \
    Kw7 = __hfma2(h7_, (DW), Kw7); Kx7 = __hfma2(h7_, (DX), Kx7); \
    Ku8 = __hfma2(h8_, (DU), Ku8); Kv8 = __hfma2(h8_, (DV), Kv8); \
    Kw8 = __hfma2(h8_, (DW), Kw8); Kx8 = __hfma2(h8_, (DX), Kx8); \
    Ku9 = __hfma2(h9_, (DU), Ku9); Kv9 = __hfma2(h9_, (DV), Kv9); \
    Kw9 = __hfma2(h9_, (DW), Kw9); Kx9 = __hfma2(h9_, (DX), Kx9); }

// Channels 2K and 2K+1: dup low/high halves of H pair K of each elem.
#define HCH4(SW, K) { \
    __half2 du_ = __low2half2(Hhu##K), dv_ = __low2half2(Hhv##K); \
    __half2 dw_ = __low2half2(Hhw##K), dx_ = __low2half2(Hhx##K); \
    HACCROW4(&(SW)[2 * (K)][0], du_, dv_, dw_, dx_); \
    du_ = __high2half2(Hhu##K); dv_ = __high2half2(Hhv##K); \
    dw_ = __high2half2(Hhw##K); dx_ = __high2half2(Hhx##K); \
    HACCROW4(&(SW)[2 * (K) + 1][0], du_, dv_, dw_, dx_); }

#define HLAYER20(SW) \
    HCH4(SW, 0) HCH4(SW, 1) HCH4(SW, 2) HCH4(SW, 3) HCH4(SW, 4) \
    HCH4(SW, 5) HCH4(SW, 6) HCH4(SW, 7) HCH4(SW, 8) HCH4(SW, 9)

#define HBIAS4(SB) { \
    const uint4* b_ = (const uint4*)(SB); \
    uint4 q0 = b_[0], q1 = b_[1], q2 = b_[2]; \
    Ku0 = u2h(q0.x); Ku1 = u2h(q0.y); Ku2 = u2h(q0.z); Ku3 = u2h(q0.w); \
    Ku4 = u2h(q1.x); Ku5 = u2h(q1.y); Ku6 = u2h(q1.z); Ku7 = u2h(q1.w); \
    Ku8 = u2h(q2.x); Ku9 = u2h(q2.y); \
    Kv0 = Ku0; Kv1 = Ku1; Kv2 = Ku2; Kv3 = Ku3; Kv4 = Ku4; \
    Kv5 = Ku5; Kv6 = Ku6; Kv7 = Ku7; Kv8 = Ku8; Kv9 = Ku9; \
    Kw0 = Ku0; Kw1 = Ku1; Kw2 = Ku2; Kw3 = Ku3; Kw4 = Ku4; \
    Kw5 = Ku5; Kw6 = Ku6; Kw7 = Ku7; Kw8 = Ku8; Kw9 = Ku9; \
    Kx0 = Ku0; Kx1 = Ku1; Kx2 = Ku2; Kx3 = Ku3; Kx4 = Ku4; \
    Kx5 = Ku5; Kx6 = Ku6; Kx7 = Ku7; Kx8 = Ku8; Kx9 = Ku9; }

#define HRELU4() \
    Hhu0 = __hmax2(Ku0, hz); Hhu1 = __hmax2(Ku1, hz); \
    Hhu2 = __hmax2(Ku2, hz); Hhu3 = __hmax2(Ku3, hz); \
    Hhu4 = __hmax2(Ku4, hz); Hhu5 = __hmax2(Ku5, hz); \
    Hhu6 = __hmax2(Ku6, hz); Hhu7 = __hmax2(Ku7, hz); \
    Hhu8 = __hmax2(Ku8, hz); Hhu9 = __hmax2(Ku9, hz); \
    Hhv0 = __hmax2(Kv0, hz); Hhv1 = __hmax2(Kv1, hz); \
    Hhv2 = __hmax2(Kv2, hz); Hhv3 = __hmax2(Kv3, hz); \
    Hhv4 = __hmax2(Kv4, hz); Hhv5 = __hmax2(Kv5, hz); \
    Hhv6 = __hmax2(Kv6, hz); Hhv7 = __hmax2(Kv7, hz); \
    Hhv8 = __hmax2(Kv8, hz); Hhv9 = __hmax2(Kv9, hz); \
    Hhw0 = __hmax2(Kw0, hz); Hhw1 = __hmax2(Kw1, hz); \
    Hhw2 = __hmax2(Kw2, hz); Hhw3 = __hmax2(Kw3, hz); \
    Hhw4 = __hmax2(Kw4, hz); Hhw5 = __hmax2(Kw5, hz); \
    Hhw6 = __hmax2(Kw6, hz); Hhw7 = __hmax2(Kw7, hz); \
    Hhw8 = __hmax2(Kw8, hz); Hhw9 = __hmax2(Kw9, hz); \
    Hhx0 = __hmax2(Kx0, hz); Hhx1 = __hmax2(Kx1, hz); \
    Hhx2 = __hmax2(Kx2, hz); Hhx3 = __hmax2(Kx3, hz); \
    Hhx4 = __hmax2(Kx4, hz); Hhx5 = __hmax2(Kx5, hz); \
    Hhx6 = __hmax2(Kx6, hz); Hhx7 = __hmax2(Kx7, hz); \
    Hhx8 = __hmax2(Kx8, hz); Hhx9 = __hmax2(Kx9, hz);

#define DECLH10(P) \
    __half2 P##0, P##1, P##2, P##3, P##4, P##5, P##6, P##7, P##8, P##9;

__global__ void __launch_bounds__(MAIN_THREADS, 2) main_kernel(
    const float* __restrict__ grad, const float* __restrict__ s0,
    const float* __restrict__ s1, const float* __restrict__ gp,
    const float* __restrict__ ex,
    const float* __restrict__ cw0, const float* __restrict__ cb0,
    const float* __restrict__ cw1, const float* __restrict__ cb1,
    const float* __restrict__ cw2, const float* __restrict__ cb2,
    const float* __restrict__ cw3, const float* __restrict__ cb3,
    float* __restrict__ out, int n) {
    // layer 0 (fp32): half-rows of 5 natural float2 pairs, padded to 48 B
    __shared__ __align__(16) float2 sw0a[4][6], sw0b[4][6];
    __shared__ __align__(16) float2 sb0a[6], sb0b[6];
    // layers 1..3 (fp16): natural half2 rows padded to 12 entries (48 B)
    __shared__ __align__(16) __half2 sw1h[20][12];
    __shared__ __align__(16) __half2 sw2h[20][12];
    __shared__ __align__(16) __half2 sw3h[12];
    __shared__ __align__(16) __half2 sb1h[12];
    __shared__ __align__(16) __half2 sb2h[12];
    __shared__ float sb3f;

    int tid = threadIdx.x;
    __half2 hz = __float2half2_rn(0.0f);

    // ---- stage weights ----
    if (tid < 24) {
        int c = tid / 6, j = tid % 6;
        float c0 = g_coeff0, c1 = g_coeff1, c2 = g_coeff2, c3 = g_coeff3;
        float cf = (c == 0) ? c0 : (c == 1) ? c1 : (c == 2) ? c2 : c3;
        sw0a[c][j] = (j < 5) ? make_float2(cw0[(2 * j) * 4 + c] * cf,
                                           cw0[(2 * j + 1) * 4 + c] * cf)
                             : make_float2(0.f, 0.f);
        sw0b[c][j] = (j < 5) ? make_float2(cw0[(10 + 2 * j) * 4 + c] * cf,
                                           cw0[(11 + 2 * j) * 4 + c] * cf)
                             : make_float2(0.f, 0.f);
    }
    for (int k = tid; k < 240; k += MAIN_THREADS) {
        int c = k / 12, j = k % 12;
        sw1h[c][j] = (j < 10) ? __floats2half2_rn(cw1[(2 * j) * 20 + c],
                                                  cw1[(2 * j + 1) * 20 + c]) : hz;
        sw2h[c][j] = (j < 10) ? __floats2half2_rn(cw2[(2 * j) * 20 + c],
                                                  cw2[(2 * j + 1) * 20 + c]) : hz;
    }
    if (tid < 12) {
        sb1h[tid] = (tid < 10) ? __floats2half2_rn(cb1[2 * tid], cb1[2 * tid + 1]) : hz;
        sb2h[tid] = (tid < 10) ? __floats2half2_rn(cb2[2 * tid], cb2[2 * tid + 1]) : hz;
        sw3h[tid] = (tid < 10) ? __floats2half2_rn(cw3[2 * tid], cw3[2 * tid + 1]) : hz;
    }
    if (tid < 6) {
        sb0a[tid] = (tid < 5) ? make_float2(cb0[2 * tid], cb0[2 * tid + 1])
                              : make_float2(0.f, 0.f);
        sb0b[tid] = (tid < 5) ? make_float2(cb0[10 + 2 * tid], cb0[11 + 2 * tid])
                              : make_float2(0.f, 0.f);
    }
    if (tid == 0) sb3f = cb3[0];
    __syncthreads();

    int i = blockIdx.x * MAIN_THREADS + tid;   // index into float4 arrays
    int nq = n >> 2;
    if (i >= nq) return;

    float inv_gn = g_inv_gn, inv_dn = g_inv_dn, fs = g_fscale;

    float4 g4 = ((const float4*)grad)[i];
    float4 a4 = ((const float4*)s0)[i];
    float4 b4 = ((const float4*)s1)[i];
    float4 p4 = ((const float4*)gp)[i];
    float4 e4 = ((const float4*)ex)[i];

    float gxu = g4.x * inv_gn, gxv = g4.y * inv_gn;
    float gxw = g4.z * inv_gn, gxx = g4.w * inv_gn;
    float dxu = (b4.x - a4.x) * inv_dn, dxv = (b4.y - a4.y) * inv_dn;
    float dxw = (b4.z - a4.z) * inv_dn, dxx = (b4.w - a4.w) * inv_dn;

    // duplicated f32x2 channel values (reused across both layer-0 halves)
    u64 d0u = pk(p4.x * gxu, p4.x * gxu), d0v = pk(p4.y * gxv, p4.y * gxv);
    u64 d0w = pk(p4.z * gxw, p4.z * gxw), d0x = pk(p4.w * gxx, p4.w * gxx);
    u64 d1u = pk(e4.x * dxu, e4.x * dxu), d1v = pk(e4.y * dxv, e4.y * dxv);
    u64 d1w = pk(e4.z * dxw, e4.z * dxw), d1x = pk(e4.w * dxx, e4.w * dxx);
    u64 d2u = pk(gxu, gxu), d2v = pk(gxv, gxv);
    u64 d2w = pk(gxw, gxw), d2x = pk(gxx, gxx);
    u64 d3u = pk(dxu, dxu), d3v = pk(dxv, dxv);
    u64 d3w = pk(dxw, dxw), d3x = pk(dxx, dxx);

    u64 Pu0, Pu1, Pu2, Pu3, Pu4;
    u64 Pv0, Pv1, Pv2, Pv3, Pv4;
    u64 Pw0, Pw1, Pw2, Pw3, Pw4;
    u64 Px0, Px1, Px2, Px3, Px4;
    DECLH10(Hhu) DECLH10(Hhv) DECLH10(Hhw) DECLH10(Hhx)
    DECLH10(Ku) DECLH10(Kv) DECLH10(Kw) DECLH10(Kx)

    // ---- layer 0 (fp32): half A -> Hh*[0..4], half B -> Hh*[5..9] ----
    BIAS5(sb0a)
    ACC5(&sw0a[0][0], d0u, d0v, d0w, d0x)
    ACC5(&sw0a[1][0], d1u, d1v, d1w, d1x)
    ACC5(&sw0a[2][0], d2u, d2v, d2w, d2x)
    ACC5(&sw0a[3][0], d3u, d3v, d3w, d3x)
    CVTHALF()  // -> Hh*0..4 via token pasting with empty BASE

    BIAS5(sb0b)
    ACC5(&sw0b[0][0], d0u, d0v, d0w, d0x)
    ACC5(&sw0b[1][0], d1u, d1v, d1w, d1x)
    ACC5(&sw0b[2][0], d2u, d2v, d2w, d2x)
    ACC5(&sw0b[3][0], d3u, d3v, d3w, d3x)
    // second half -> Hh*5..9
    Hhu5 = relucvt(Pu0); Hhu6 = relucvt(Pu1); Hhu7 = relucvt(Pu2);
    Hhu8 = relucvt(Pu3); Hhu9 = relucvt(Pu4);
    Hhv5 = relucvt(Pv0); Hhv6 = relucvt(Pv1); Hhv7 = relucvt(Pv2);
    Hhv8 = relucvt(Pv3); Hhv9 = relucvt(Pv4);
    Hhw5 = relucvt(Pw0); Hhw6 = relucvt(Pw1); Hhw7 = relucvt(Pw2);
    Hhw8 = relucvt(Pw3); Hhw9 = relucvt(Pw4);
    Hhx5 = relucvt(Px0); Hhx6 = relucvt(Px1); Hhx7 = relucvt(Px2);
    Hhx8 = relucvt(Px3); Hhx9 = relucvt(Px4);

    // ---- layer 1 (fp16) ----
    HBIAS4(sb1h)
    HLAYER20(sw1h)
    HRELU4()

    // ---- layer 2 (fp16) ----
    HBIAS4(sb2h)
    HLAYER20(sw2h)
    HRELU4()

    // ---- layer 3 (fp16 dot, fp32 finish) ----
    __half2 au = hz, av = hz, aw = hz, ax = hz;
    {
        const uint4* r_ = (const uint4*)sw3h;
        uint4 q0 = r_[0], q1 = r_[1], q2 = r_[2];
        __half2 h0_ = u2h(q0.x), h1_ = u2h(q0.y), h2_ = u2h(q0.z), h3_ = u2h(q0.w);
        __half2 h4_ = u2h(q1.x), h5_ = u2h(q1.y), h6_ = u2h(q1.z), h7_ = u2h(q1.w);
        __half2 h8_ = u2h(q2.x), h9_ = u2h(q2.y);
        au = __hfma2(h0_, Hhu0, au); av = __hfma2(h0_, Hhv0, av);
        aw = __hfma2(h0_, Hhw0, aw); ax = __hfma2(h0_, Hhx0, ax);
        au = __hfma2(h1_, Hhu1, au); av = __hfma2(h1_, Hhv1, av);
        aw = __hfma2(h1_, Hhw1, aw); ax = __hfma2(h1_, Hhx1, ax);
        au = __hfma2(h2_, Hhu2, au); av = __hfma2(h2_, Hhv2, av);
        aw = __hfma2(h2_, Hhw2, aw); ax = __hfma2(h2_, Hhx2, ax);
        au = __hfma2(h3_, Hhu3, au); av = __hfma2(h3_, Hhv3, av);
        aw = __hfma2(h3_, Hhw3, aw); ax = __hfma2(h3_, Hhx3, ax);
        au = __hfma2(h4_, Hhu4, au); av = __hfma2(h4_, Hhv4, av);
        aw = __hfma2(h4_, Hhw4, aw); ax = __hfma2(h4_, Hhx4, ax);
        au = __hfma2(h5_, Hhu5, au); av = __hfma2(h5_, Hhv5, av);
        aw = __hfma2(h5_, Hhw5, aw); ax = __hfma2(h5_, Hhx5, ax);
        au = __hfma2(h6_, Hhu6, au); av = __hfma2(h6_, Hhv6, av);
        aw = __hfma2(h6_, Hhw6, aw); ax = __hfma2(h6_, Hhx6, ax);
        au = __hfma2(h7_, Hhu7, au); av = __hfma2(h7_, Hhv7, av);
        aw = __hfma2(h7_, Hhw7, aw); ax = __hfma2(h7_, Hhx7, ax);
        au = __hfma2(h8_, Hhu8, au); av = __hfma2(h8_, Hhv8, av);
        aw = __hfma2(h8_, Hhw8, aw); ax = __hfma2(h8_, Hhx8, ax);
        au = __hfma2(h9_, Hhu9, au); av = __hfma2(h9_, Hhv9, av);
        aw = __hfma2(h9_, Hhw9, aw); ax = __hfma2(h9_, Hhx9, ax);
    }
    float cb3v = sb3f;
    float2 fu = __half22float2(au), fv = __half22float2(av);
    float2 fw = __half22float2(aw), fx = __half22float2(ax);
    float4 o4;
    o4.x = fmaf(fu.x + fu.y + cb3v, fs, b4.x);
    o4.y = fmaf(fv.x + fv.y + cb3v, fs, b4.y);
    o4.z = fmaf(fw.x + fw.y + cb3v, fs, b4.z);
    o4.w = fmaf(fx.x + fx.y + cb3v, fs, b4.w);
    ((float4*)out)[i] = o4;
}

// ---------------------------------------------------------------------------
extern "C" void kernel_launch(void* const* d_in, const int* in_sizes, int n_in,
                              void* d_out, int out_size) {
    const float* grad = (const float*)d_in[0];
    const float* s0   = (const float*)d_in[1];
    const float* s1   = (const float*)d_in[2];
    const float* loss_cur = (const float*)d_in[3];
    const float* loss_old = (const float*)d_in[4];
    const int*   iter_p   = (const int*)d_in[5];
    const float* gp = (const float*)d_in[6];
    const float* ex = (const float*)d_in[7];
    const float* cw0 = (const float*)d_in[8];
    const float* cb0 = (const float*)d_in[9];
    const float* cw1 = (const float*)d_in[10];
    const float* cb1 = (const float*)d_in[11];
    const float* cw2 = (const float*)d_in[12];
    const float* cb2 = (const float*)d_in[13];
    const float* cw3 = (const float*)d_in[14];
    const float* cb3 = (const float*)d_in[15];
    const float* lw0 = (const float*)d_in[16];
    const float* lb0 = (const float*)d_in[17];
    const float* lw1 = (const float*)d_in[18];
    const float* lb1 = (const float*)d_in[19];
    const float* lw2 = (const float*)d_in[20];
    const float* lb2 = (const float*)d_in[21];
    const float* lw3 = (const float*)d_in[22];
    const float* lb3 = (const float*)d_in[23];

    int n = in_sizes[0];
    int nq = n >> 2;
    int main_blocks = (nq + MAIN_THREADS - 1) / MAIN_THREADS;
    if (main_blocks < 1) main_blocks = 1;

    reduce_scalars_kernel<<<RED_BLOCKS, RED_THREADS>>>(
        grad, s0, s1, n, loss_cur, loss_old, iter_p,
        lw0, lb0, lw1, lb1, lw2, lb2, lw3, lb3);
    main_kernel<<<main_blocks, MAIN_THREADS>>>(grad, s0, s1, gp, ex,
                                               cw0, cb0, cw1, cb1, cw2, cb2,
                                               cw3, cb3, (float*)d_out, n);
}